// round 1
// baseline (speedup 1.0000x reference)
#include <cuda_runtime.h>
#include <cuda_bf16.h>
#include <math.h>

// ---------------- problem constants ----------------
#define NUM_SUBNETS 8
#define REGIONS     50
#define TOTAL_R     400
#define HIDDEN      512
#define HEADS       8
#define HEAD_DIM    64
#define BATCH       256
#define FLAT        2500
#define ROWS        (NUM_SUBNETS * BATCH)   // 2048 rows, r = s*256 + b
#define LN_EPS      1e-5f

typedef unsigned long long u64;

// ---------------- scratch (device globals, alloc-free) ----------------
__device__ float g_flat[NUM_SUBNETS * BATCH * FLAT];   // [s][b][2500]
__device__ float g_h   [ROWS * HIDDEN];
__device__ float g_xsub[ROWS * HIDDEN];
__device__ float g_xn  [ROWS * HIDDEN];
__device__ float g_q   [ROWS * HIDDEN];
__device__ float g_k   [ROWS * HIDDEN];
__device__ float g_v   [ROWS * HIDDEN];
__device__ float g_ctx [ROWS * HIDDEN];
__device__ float g_t   [ROWS * HIDDEN];

// ---------------- f32x2 helpers (sm_100+) ----------------
__device__ __forceinline__ u64 pack2(float lo, float hi) {
    u64 r; asm("mov.b64 %0, {%1,%2};" : "=l"(r) : "f"(lo), "f"(hi)); return r;
}
__device__ __forceinline__ void unpack2(u64 p, float& lo, float& hi) {
    asm("mov.b64 {%0,%1}, %2;" : "=f"(lo), "=f"(hi) : "l"(p));
}
__device__ __forceinline__ void ffma2(u64& d, u64 a, u64 b) {
    asm("fma.rn.f32x2 %0, %1, %2, %0;" : "+l"(d) : "l"(a), "l"(b));
}

// ---------------- kernel 0: diagonal-block extraction ----------------
// g_flat[s][b][i*50+j] = x[b, s*50+i, s*50+j]
__global__ void extract_kernel(const float* __restrict__ x) {
    int idx = blockIdx.x * blockDim.x + threadIdx.x;
    if (idx >= NUM_SUBNETS * BATCH * FLAT) return;
    int f  = idx % FLAT;
    int sb = idx / FLAT;
    int b  = sb & (BATCH - 1);
    int s  = sb >> 8;
    int i  = f / REGIONS;
    int j  = f - i * REGIONS;
    g_flat[idx] = x[(size_t)b * (TOTAL_R * TOTAL_R) + (s * REGIONS + i) * TOTAL_R + (s * REGIONS + j)];
}

// ---------------- generic 64x64 tile GEMM, f32x2 inner loop ----------------
// C[row][n] = A[row][0:K] * W[(s?)][K][512] + bias ; EP: 0 none, 1 relu, 2 residual+permuted store
template<int EP>
__global__ __launch_bounds__(256) void gemm64(
    const float* __restrict__ A, const float* __restrict__ W,
    const float* __restrict__ bias, float* __restrict__ C,
    int K, int subnet, const float* __restrict__ resid)
{
    __shared__ u64 As2[16][68];   // [kk][m], value duplicated in both halves
    __shared__ u64 Bs2[16][32];   // [kk][n/2], adjacent column pairs

    int tid = threadIdx.x;
    int tx = tid & 15, ty = tid >> 4;
    int mBase = blockIdx.y * 64, nBase = blockIdx.x * 64;
    int sIdx = subnet ? (int)(blockIdx.y >> 2) : 0;   // 256 rows (4 y-blocks) per subnet
    const float* Wp = W + (size_t)sIdx * K * HIDDEN;
    const float* bp = bias + sIdx * HIDDEN;

    int am  = tid >> 2;           // 0..63
    int ak  = (tid & 3) << 2;     // 0,4,8,12
    int bk  = tid >> 4;           // 0..15
    int bn2 = (tid & 15) * 2;     // u64 column

    u64 acc[4][2];
    #pragma unroll
    for (int i = 0; i < 4; i++) { acc[i][0] = 0ull; acc[i][1] = 0ull; }

    const float* Arow = A + (size_t)(mBase + am) * K;
    for (int k0 = 0; k0 < K; k0 += 16) {
        #pragma unroll
        for (int j = 0; j < 4; j++) {
            int kk = ak + j;
            float v = (k0 + kk < K) ? Arow[k0 + kk] : 0.f;
            As2[kk][am] = pack2(v, v);
        }
        if (k0 + bk < K) {
            float4 w = *(const float4*)(Wp + (size_t)(k0 + bk) * HIDDEN + nBase + bn2 * 2);
            Bs2[bk][bn2]     = pack2(w.x, w.y);
            Bs2[bk][bn2 + 1] = pack2(w.z, w.w);
        } else {
            Bs2[bk][bn2] = 0ull; Bs2[bk][bn2 + 1] = 0ull;
        }
        __syncthreads();
        #pragma unroll
        for (int kk = 0; kk < 16; kk++) {
            u64 a0 = As2[kk][ty * 4 + 0];
            u64 a1 = As2[kk][ty * 4 + 1];
            u64 a2 = As2[kk][ty * 4 + 2];
            u64 a3 = As2[kk][ty * 4 + 3];
            u64 b0 = Bs2[kk][tx * 2];
            u64 b1 = Bs2[kk][tx * 2 + 1];
            ffma2(acc[0][0], a0, b0); ffma2(acc[0][1], a0, b1);
            ffma2(acc[1][0], a1, b0); ffma2(acc[1][1], a1, b1);
            ffma2(acc[2][0], a2, b0); ffma2(acc[2][1], a2, b1);
            ffma2(acc[3][0], a3, b0); ffma2(acc[3][1], a3, b1);
        }
        __syncthreads();
    }

    #pragma unroll
    for (int i = 0; i < 4; i++) {
        int row = mBase + ty * 4 + i;
        #pragma unroll
        for (int j = 0; j < 2; j++) {
            float lo, hi; unpack2(acc[i][j], lo, hi);
            int col = nBase + tx * 4 + j * 2;
            lo += bp[col]; hi += bp[col + 1];
            if (EP == 1) { lo = fmaxf(lo, 0.f); hi = fmaxf(hi, 0.f); }
            if (EP == 2) {
                int bb = row & (BATCH - 1), ss = row >> 8;
                size_t o  = ((size_t)((bb << 3) + ss)) * HIDDEN + col;   // (b, s, h) order
                size_t rr = (size_t)row * HIDDEN + col;
                C[o]     = lo + resid[rr];
                C[o + 1] = hi + resid[rr + 1];
            } else {
                C[(size_t)row * HIDDEN + col]     = lo;
                C[(size_t)row * HIDDEN + col + 1] = hi;
            }
        }
    }
}

// ---------------- LayerNorm (one block per row) ----------------
__global__ __launch_bounds__(256) void ln_kernel(const float* __restrict__ lng,
                                                 const float* __restrict__ lnb)
{
    int r = blockIdx.x, t = threadIdx.x;
    const float* xs = g_xsub + (size_t)r * HIDDEN;
    float v0 = xs[t], v1 = xs[t + 256];
    float s = v0 + v1, q = v0 * v0 + v1 * v1;
    // warp + block reduce
    #pragma unroll
    for (int o = 16; o > 0; o >>= 1) {
        s += __shfl_xor_sync(0xFFFFFFFFu, s, o);
        q += __shfl_xor_sync(0xFFFFFFFFu, q, o);
    }
    __shared__ float ss[8], sq[8];
    int w = t >> 5, l = t & 31;
    if (l == 0) { ss[w] = s; sq[w] = q; }
    __syncthreads();
    if (w == 0) {
        float a = (l < 8) ? ss[l] : 0.f;
        float c = (l < 8) ? sq[l] : 0.f;
        #pragma unroll
        for (int o = 4; o > 0; o >>= 1) {
            a += __shfl_xor_sync(0xFFFFFFFFu, a, o);
            c += __shfl_xor_sync(0xFFFFFFFFu, c, o);
        }
        if (l == 0) { ss[0] = a; sq[0] = c; }
    }
    __syncthreads();
    float mean = ss[0] * (1.f / HIDDEN);
    float var  = sq[0] * (1.f / HIDDEN) - mean * mean;
    float inv  = rsqrtf(var + LN_EPS);
    float* out = g_xn + (size_t)r * HIDDEN;
    out[t]       = (v0 - mean) * inv * lng[t]       + lnb[t];
    out[t + 256] = (v1 - mean) * inv * lng[t + 256] + lnb[t + 256];
}

// ---------------- attention: one block per batch, one warp per head ----------------
__global__ __launch_bounds__(256) void attn_kernel()
{
    __shared__ float q_s[NUM_SUBNETS][520];
    __shared__ float k_s[NUM_SUBNETS][520];
    __shared__ float sc[HEADS][NUM_SUBNETS][NUM_SUBNETS];

    int b = blockIdx.x;
    int tid = threadIdx.x;

    // cooperative load q,k for this batch across all 8 subnets
    for (int i = tid; i < NUM_SUBNETS * HIDDEN; i += 256) {
        int m = i >> 9, c = i & 511;
        size_t gi = ((size_t)(m * BATCH + b)) * HIDDEN + c;
        q_s[m][c] = g_q[gi];
        k_s[m][c] = g_k[gi];
    }
    __syncthreads();

    int h = tid >> 5, l = tid & 31;

    // scores (2 (m,n) pairs per lane)
    #pragma unroll
    for (int pp = 0; pp < 2; pp++) {
        int p = l + pp * 32;
        int m = p >> 3, n = p & 7;
        const float* qp = &q_s[m][h * HEAD_DIM];
        const float* kp = &k_s[n][h * HEAD_DIM];
        float sv = 0.f;
        #pragma unroll
        for (int d = 0; d < HEAD_DIM; d++) sv += qp[d] * kp[d];
        sv *= 0.125f;                 // 1/sqrt(64)
        sc[h][m][n] = (m == n) ? 0.f : sv;
    }
    __syncwarp();

    // softmax per row
    if (l < NUM_SUBNETS) {
        float mx = -1e30f;
        #pragma unroll
        for (int n = 0; n < 8; n++) mx = fmaxf(mx, sc[h][l][n]);
        float e[8], sum = 0.f;
        #pragma unroll
        for (int n = 0; n < 8; n++) { e[n] = expf(sc[h][l][n] - mx); sum += e[n]; }
        float inv = 1.f / sum;
        #pragma unroll
        for (int n = 0; n < 8; n++) sc[h][l][n] = e[n] * inv;
    }
    __syncwarp();

    // ctx = attn @ v  (lane handles d = l and l+32)
    #pragma unroll
    for (int dd = 0; dd < 2; dd++) {
        int d = l + dd * 32;
        float vv[8];
        #pragma unroll
        for (int n = 0; n < 8; n++)
            vv[n] = g_v[((size_t)(n * BATCH + b)) * HIDDEN + h * HEAD_DIM + d];
        #pragma unroll
        for (int m = 0; m < 8; m++) {
            float cv = 0.f;
            #pragma unroll
            for (int n = 0; n < 8; n++) cv += sc[h][m][n] * vv[n];
            g_ctx[((size_t)(m * BATCH + b)) * HIDDEN + h * HEAD_DIM + d] = cv;
        }
    }
}

// ---------------- launch ----------------
extern "C" void kernel_launch(void* const* d_in, const int* in_sizes, int n_in,
                              void* d_out, int out_size)
{
    (void)in_sizes; (void)n_in;
    const float* x    = (const float*)d_in[0];
    // d_in[1] = subnet_masks (bool) — fixed diagonal blocks, unused
    const float* W1   = (const float*)d_in[2];
    const float* b1   = (const float*)d_in[3];
    const float* W2   = (const float*)d_in[4];
    const float* b2   = (const float*)d_in[5];
    const float* ln_g = (const float*)d_in[6];
    const float* ln_b = (const float*)d_in[7];
    const float* Wq   = (const float*)d_in[8];
    const float* bq   = (const float*)d_in[9];
    const float* Wk   = (const float*)d_in[10];
    const float* bk   = (const float*)d_in[11];
    const float* Wv   = (const float*)d_in[12];
    const float* bv   = (const float*)d_in[13];
    const float* Wo   = (const float*)d_in[14];
    const float* bo   = (const float*)d_in[15];
    const float* Wp   = (const float*)d_in[16];
    const float* bp   = (const float*)d_in[17];
    float* out = (float*)d_out;
    (void)out_size;

    float *p_flat, *p_h, *p_xsub, *p_xn, *p_q, *p_k, *p_v, *p_ctx, *p_t;
    cudaGetSymbolAddress((void**)&p_flat, g_flat);
    cudaGetSymbolAddress((void**)&p_h,    g_h);
    cudaGetSymbolAddress((void**)&p_xsub, g_xsub);
    cudaGetSymbolAddress((void**)&p_xn,   g_xn);
    cudaGetSymbolAddress((void**)&p_q,    g_q);
    cudaGetSymbolAddress((void**)&p_k,    g_k);
    cudaGetSymbolAddress((void**)&p_v,    g_v);
    cudaGetSymbolAddress((void**)&p_ctx,  g_ctx);
    cudaGetSymbolAddress((void**)&p_t,    g_t);

    dim3 gemmGrid(HIDDEN / 64, ROWS / 64);   // 8 x 32

    int nExtract = NUM_SUBNETS * BATCH * FLAT;
    extract_kernel<<<(nExtract + 255) / 256, 256>>>(x);

    gemm64<1><<<gemmGrid, 256>>>(p_flat, W1, b1, p_h,    FLAT,   1, nullptr);  // h = relu(flat@W1+b1)
    gemm64<0><<<gemmGrid, 256>>>(p_h,    W2, b2, p_xsub, HIDDEN, 1, nullptr);  // x_sub
    ln_kernel<<<ROWS, 256>>>(ln_g, ln_b);                                      // xn
    gemm64<0><<<gemmGrid, 256>>>(p_xn, Wq, bq, p_q, HIDDEN, 0, nullptr);
    gemm64<0><<<gemmGrid, 256>>>(p_xn, Wk, bk, p_k, HIDDEN, 0, nullptr);
    gemm64<0><<<gemmGrid, 256>>>(p_xn, Wv, bv, p_v, HIDDEN, 0, nullptr);
    attn_kernel<<<BATCH, 256>>>();                                             // ctx
    gemm64<0><<<gemmGrid, 256>>>(p_ctx, Wo, bo, p_t, HIDDEN, 0, nullptr);
    gemm64<2><<<gemmGrid, 256>>>(p_t,   Wp, bp, out, HIDDEN, 0, p_xsub);       // out = t@Wp+bp+x_sub, (b,s) order
}

// round 3
// speedup vs baseline: 2.7850x; 2.7850x over previous
#include <cuda_runtime.h>
#include <cuda_bf16.h>
#include <math.h>
#include <cstdint>

// ---------------- problem constants ----------------
#define NUM_SUBNETS 8
#define REGIONS     50
#define TOTAL_R     400
#define HIDDEN      512
#define HEADS       8
#define HEAD_DIM    64
#define BATCH       256
#define FLAT        2500
#define ROWS        (NUM_SUBNETS * BATCH)   // 2048
#define LN_EPS      1e-5f
#define KPAD1       2560                    // FLAT padded to multiple of 32

// GEMM tiling
#define BM 128
#define BN 64
#define BK 32
#define ASTRIDE 80                          // bytes per 32-col bf16 row (64 + 16 pad)
#define A_BYTES (BM * ASTRIDE)              // 10240
#define B_BYTES (BN * ASTRIDE)              // 5120
#define STAGE   (2 * A_BYTES + 2 * B_BYTES) // 30720
#define GEMM_SMEM (2 * STAGE)               // 61440

typedef unsigned long long u64;

// ---------------- scratch (device globals) ----------------
__device__ __nv_bfloat16 g_flat_hi[ROWS * KPAD1];
__device__ __nv_bfloat16 g_flat_lo[ROWS * KPAD1];
__device__ __nv_bfloat16 g_W1T_hi[NUM_SUBNETS * HIDDEN * KPAD1];
__device__ __nv_bfloat16 g_W1T_lo[NUM_SUBNETS * HIDDEN * KPAD1];
__device__ __nv_bfloat16 g_W2T_hi[NUM_SUBNETS * HIDDEN * HIDDEN];
__device__ __nv_bfloat16 g_W2T_lo[NUM_SUBNETS * HIDDEN * HIDDEN];
__device__ __nv_bfloat16 g_WqkvT_hi[3 * HIDDEN * HIDDEN];
__device__ __nv_bfloat16 g_WqkvT_lo[3 * HIDDEN * HIDDEN];
__device__ __nv_bfloat16 g_WoT_hi[HIDDEN * HIDDEN];
__device__ __nv_bfloat16 g_WoT_lo[HIDDEN * HIDDEN];
__device__ __nv_bfloat16 g_WpT_hi[HIDDEN * HIDDEN];
__device__ __nv_bfloat16 g_WpT_lo[HIDDEN * HIDDEN];

__device__ __nv_bfloat16 g_h_hi[ROWS * HIDDEN];
__device__ __nv_bfloat16 g_h_lo[ROWS * HIDDEN];
__device__ float         g_xsub[ROWS * HIDDEN];
__device__ __nv_bfloat16 g_xn_hi[ROWS * HIDDEN];
__device__ __nv_bfloat16 g_xn_lo[ROWS * HIDDEN];
__device__ float         g_q[ROWS * HIDDEN];
__device__ float         g_k[ROWS * HIDDEN];
__device__ float         g_v[ROWS * HIDDEN];
__device__ __nv_bfloat16 g_ctx_hi[ROWS * HIDDEN];
__device__ __nv_bfloat16 g_ctx_lo[ROWS * HIDDEN];
__device__ __nv_bfloat16 g_t_hi[ROWS * HIDDEN];
__device__ __nv_bfloat16 g_t_lo[ROWS * HIDDEN];

// ---------------- PTX helpers (all sm_80-ratified; NO 'a'-only features) ----------------
__device__ __forceinline__ uint32_t smem_u32(const void* p) {
    uint32_t a;
    asm("{ .reg .u64 t; cvta.to.shared.u64 t, %1; cvt.u32.u64 %0, t; }" : "=r"(a) : "l"(p));
    return a;
}
__device__ __forceinline__ void cpa16(uint32_t s, const void* g) {
    asm volatile("cp.async.cg.shared.global [%0], [%1], 16;" :: "r"(s), "l"(g));
}
__device__ __forceinline__ void cpa_commit() {
    asm volatile("cp.async.commit_group;" ::: "memory");
}
template<int N> __device__ __forceinline__ void cpa_wait() {
    asm volatile("cp.async.wait_group %0;" :: "n"(N) : "memory");
}
__device__ __forceinline__ void ldm4(uint32_t a, uint32_t* r) {
    asm volatile("ldmatrix.sync.aligned.m8n8.x4.shared.b16 {%0,%1,%2,%3}, [%4];"
        : "=r"(r[0]), "=r"(r[1]), "=r"(r[2]), "=r"(r[3]) : "r"(a));
}
__device__ __forceinline__ void mma16816(float* c, const uint32_t* a, uint32_t b0, uint32_t b1) {
    asm volatile("mma.sync.aligned.m16n8k16.row.col.f32.bf16.bf16.f32 "
        "{%0,%1,%2,%3},{%4,%5,%6,%7},{%8,%9},{%0,%1,%2,%3};"
        : "+f"(c[0]), "+f"(c[1]), "+f"(c[2]), "+f"(c[3])
        : "r"(a[0]), "r"(a[1]), "r"(a[2]), "r"(a[3]), "r"(b0), "r"(b1));
}

__device__ __forceinline__ void store_hilo(__nv_bfloat16* hi, __nv_bfloat16* lo,
                                           size_t off, float v0, float v1) {
    __nv_bfloat16 h0 = __float2bfloat16(v0);
    __nv_bfloat16 h1 = __float2bfloat16(v1);
    __nv_bfloat16 l0 = __float2bfloat16(v0 - __bfloat162float(h0));
    __nv_bfloat16 l1 = __float2bfloat16(v1 - __bfloat162float(h1));
    __nv_bfloat162 hp; hp.x = h0; hp.y = h1;
    __nv_bfloat162 lp; lp.x = l0; lp.y = l1;
    *(__nv_bfloat162*)(hi + off) = hp;
    *(__nv_bfloat162*)(lo + off) = lp;
}

// ---------------- kernel: extract diagonal blocks -> bf16 hi/lo (K padded) ----------------
__global__ void extract_kernel(const float* __restrict__ x) {
    int idx = blockIdx.x * blockDim.x + threadIdx.x;
    if (idx >= ROWS * KPAD1) return;
    int f  = idx % KPAD1;
    int sb = idx / KPAD1;           // s*256 + b
    int b  = sb & (BATCH - 1);
    int s  = sb >> 8;
    float v = 0.f;
    if (f < FLAT) {
        int i = f / REGIONS;
        int j = f - i * REGIONS;
        v = x[(size_t)b * (TOTAL_R * TOTAL_R) + (s * REGIONS + i) * TOTAL_R + (s * REGIONS + j)];
    }
    __nv_bfloat16 hi = __float2bfloat16(v);
    g_flat_hi[idx] = hi;
    g_flat_lo[idx] = __float2bfloat16(v - __bfloat162float(hi));
}

// ---------------- kernel: weight transpose + bf16 hi/lo split ----------------
// src [z][K][N] fp32 -> dst [z][N][Kpad] bf16 (zero pad K..Kpad)
__global__ void wconv_kernel(const float* __restrict__ src,
                             __nv_bfloat16* __restrict__ dhi,
                             __nv_bfloat16* __restrict__ dlo,
                             int K, int N, int Kpad) {
    __shared__ float tile[32][33];
    int k0 = blockIdx.x * 32, n0 = blockIdx.y * 32, z = blockIdx.z;
    const float* sp = src + (size_t)z * K * N;
    size_t dbase = (size_t)z * N * Kpad;
    int tx = threadIdx.x, ty = threadIdx.y;   // 32 x 8
    #pragma unroll
    for (int r = 0; r < 4; r++) {
        int k = k0 + ty + r * 8;
        tile[ty + r * 8][tx] = (k < K) ? sp[(size_t)k * N + n0 + tx] : 0.f;
    }
    __syncthreads();
    #pragma unroll
    for (int r = 0; r < 4; r++) {
        int n = n0 + ty + r * 8;
        float v = tile[tx][ty + r * 8];
        __nv_bfloat16 hi = __float2bfloat16(v);
        size_t o = dbase + (size_t)n * Kpad + k0 + tx;
        dhi[o] = hi;
        dlo[o] = __float2bfloat16(v - __bfloat162float(hi));
    }
}

// ---------------- mma.sync GEMM: C[2048][N] = A[2048][K] * W^T + epilogue ----------------
// A [2048][sA] bf16 hi/lo, B (=W^T) [N][sB] bf16 hi/lo. C = Ah*Bh + Ah*Bl + Al*Bh.
// EP: 0 relu->hi/lo | 1 f32 | 2 qkv split f32 | 3 hi/lo | 4 resid+permute f32
template<int EP>
__global__ __launch_bounds__(256) void tc_gemm(
    const __nv_bfloat16* __restrict__ Ahi, const __nv_bfloat16* __restrict__ Alo, int sA,
    const __nv_bfloat16* __restrict__ Bhi, const __nv_bfloat16* __restrict__ Blo, int sB,
    long bSub, int Ksteps,
    const float* __restrict__ bias,
    float* __restrict__ o32,
    __nv_bfloat16* __restrict__ oHi, __nv_bfloat16* __restrict__ oLo,
    const float* __restrict__ resid,
    float* __restrict__ oq, float* __restrict__ okk, float* __restrict__ ov,
    const float* __restrict__ bq, const float* __restrict__ bk, const float* __restrict__ bv)
{
    extern __shared__ __align__(128) char smem[];
    const uint32_t sbase = smem_u32(smem);
    const int tid = threadIdx.x;
    const int mBase = blockIdx.y * BM;
    const int nBase = blockIdx.x * BN;
    const int sIdx = blockIdx.y >> 1;        // 2 M-tiles (256 rows) per subnet

    const __nv_bfloat16* aH = Ahi + (size_t)mBase * sA;
    const __nv_bfloat16* aL = Alo + (size_t)mBase * sA;
    size_t boff = (bSub > 0 ? (size_t)sIdx * (size_t)bSub : 0) + (size_t)nBase * sB;
    const __nv_bfloat16* bH = Bhi + boff;
    const __nv_bfloat16* bL = Blo + boff;
    const float* biasP = bias ? (bias + (bSub > 0 ? sIdx * HIDDEN : 0)) : bias;

    // ---- async-copy one K-chunk into stage buffer ----
    auto issue = [&](int chunk) {
        const int buf = chunk & 1;
        const uint32_t st = sbase + buf * STAGE;
        const int k0 = chunk * BK;
        #pragma unroll
        for (int i = 0; i < 2; i++) {                 // A: 128 rows x 4 chunks of 16B
            int idx = tid + i * 256;
            int row = idx >> 2, c = idx & 3;
            uint32_t so = st + row * ASTRIDE + c * 16;
            const __nv_bfloat16* gh = aH + (size_t)row * sA + k0 + c * 8;
            const __nv_bfloat16* gl = aL + (size_t)row * sA + k0 + c * 8;
            cpa16(so,           gh);
            cpa16(so + A_BYTES, gl);
        }
        {                                             // B: 64 rows x 4 chunks
            int row = tid >> 2, c = tid & 3;
            uint32_t so = st + 2 * A_BYTES + row * ASTRIDE + c * 16;
            cpa16(so,           bH + (size_t)row * sB + k0 + c * 8);
            cpa16(so + B_BYTES, bL + (size_t)row * sB + k0 + c * 8);
        }
        cpa_commit();
    };

    issue(0);
    if (Ksteps > 1) issue(1);

    const int wid = tid >> 5, lane = tid & 31;
    const int wm = wid >> 1, wn = wid & 1;            // 4 x 2 warps, warp tile 32x32
    const uint32_t lrow = lane & 15;
    const uint32_t lcol = (lane >> 4) * 16;           // byte offset within 32B k-row

    float acc[2][4][4];
    #pragma unroll
    for (int i = 0; i < 2; i++)
        #pragma unroll
        for (int j = 0; j < 4; j++)
            #pragma unroll
            for (int t = 0; t < 4; t++) acc[i][j][t] = 0.f;

    for (int s = 0; s < Ksteps; ++s) {
        if (s < Ksteps - 1) cpa_wait<1>(); else cpa_wait<0>();
        __syncthreads();
        const uint32_t st = sbase + (s & 1) * STAGE;
        #pragma unroll
        for (int kk = 0; kk < 2; ++kk) {
            uint32_t aHf[2][4], aLf[2][4], bHf[2][4], bLf[2][4];
            #pragma unroll
            for (int am = 0; am < 2; am++) {
                uint32_t ad = st + (wm * 32 + am * 16 + lrow) * ASTRIDE + kk * 32 + lcol;
                ldm4(ad,           aHf[am]);
                ldm4(ad + A_BYTES, aLf[am]);
            }
            #pragma unroll
            for (int j = 0; j < 2; j++) {
                uint32_t bd = st + 2 * A_BYTES + (wn * 32 + j * 16 + lrow) * ASTRIDE + kk * 32 + lcol;
                ldm4(bd,           bHf[j]);
                ldm4(bd + B_BYTES, bLf[j]);
            }
            #pragma unroll
            for (int am = 0; am < 2; am++) {
                #pragma unroll
                for (int j = 0; j < 2; j++) {
                    mma16816(acc[am][2*j],   aHf[am], bHf[j][0], bHf[j][2]);
                    mma16816(acc[am][2*j+1], aHf[am], bHf[j][1], bHf[j][3]);
                    mma16816(acc[am][2*j],   aHf[am], bLf[j][0], bLf[j][2]);
                    mma16816(acc[am][2*j+1], aHf[am], bLf[j][1], bLf[j][3]);
                    mma16816(acc[am][2*j],   aLf[am], bHf[j][0], bHf[j][2]);
                    mma16816(acc[am][2*j+1], aLf[am], bHf[j][1], bHf[j][3]);
                }
            }
        }
        __syncthreads();
        if (s + 2 < Ksteps) issue(s + 2);
    }

    // ---- epilogue: registers -> global ----
    #pragma unroll
    for (int am = 0; am < 2; am++) {
        #pragma unroll
        for (int an = 0; an < 4; an++) {
            int m0 = mBase + wm * 32 + am * 16 + (lane >> 2);
            int g  = nBase + wn * 32 + an * 8 + (lane & 3) * 2;
            #pragma unroll
            for (int half = 0; half < 2; half++) {
                int m = m0 + half * 8;
                float v0 = acc[am][an][half * 2];
                float v1 = acc[am][an][half * 2 + 1];
                if (EP == 0) {                          // relu -> h hi/lo
                    v0 = fmaxf(v0 + biasP[g], 0.f);
                    v1 = fmaxf(v1 + biasP[g + 1], 0.f);
                    store_hilo(oHi, oLo, (size_t)m * HIDDEN + g, v0, v1);
                } else if (EP == 1) {                   // xsub fp32
                    v0 += biasP[g]; v1 += biasP[g + 1];
                    *(float2*)(o32 + (size_t)m * HIDDEN + g) = make_float2(v0, v1);
                } else if (EP == 2) {                   // qkv fp32 split
                    int which = g >> 9, lc = g & 511;
                    const float* bb = (which == 0) ? bq : (which == 1) ? bk : bv;
                    float* dst = (which == 0) ? oq : (which == 1) ? okk : ov;
                    v0 += bb[lc]; v1 += bb[lc + 1];
                    *(float2*)(dst + (size_t)m * HIDDEN + lc) = make_float2(v0, v1);
                } else if (EP == 3) {                   // t hi/lo
                    v0 += biasP[g]; v1 += biasP[g + 1];
                    store_hilo(oHi, oLo, (size_t)m * HIDDEN + g, v0, v1);
                } else {                                // out = . + bp + xsub, (b,s) order
                    v0 += biasP[g] + resid[(size_t)m * HIDDEN + g];
                    v1 += biasP[g + 1] + resid[(size_t)m * HIDDEN + g + 1];
                    int bb2 = m & (BATCH - 1), ss = m >> 8;
                    *(float2*)(o32 + ((size_t)((bb2 << 3) + ss)) * HIDDEN + g) = make_float2(v0, v1);
                }
            }
        }
    }
}

// ---------------- LayerNorm: xsub fp32 -> xn hi/lo ----------------
__global__ __launch_bounds__(256) void ln_kernel(const float* __restrict__ lng,
                                                 const float* __restrict__ lnb)
{
    int r = blockIdx.x, t = threadIdx.x;
    const float* xs = g_xsub + (size_t)r * HIDDEN;
    float v0 = xs[t], v1 = xs[t + 256];
    float s = v0 + v1, q = v0 * v0 + v1 * v1;
    #pragma unroll
    for (int o = 16; o > 0; o >>= 1) {
        s += __shfl_xor_sync(0xFFFFFFFFu, s, o);
        q += __shfl_xor_sync(0xFFFFFFFFu, q, o);
    }
    __shared__ float ss[8], sq[8];
    int w = t >> 5, l = t & 31;
    if (l == 0) { ss[w] = s; sq[w] = q; }
    __syncthreads();
    if (w == 0) {
        float a = (l < 8) ? ss[l] : 0.f;
        float c = (l < 8) ? sq[l] : 0.f;
        #pragma unroll
        for (int o = 4; o > 0; o >>= 1) {
            a += __shfl_xor_sync(0xFFFFFFFFu, a, o);
            c += __shfl_xor_sync(0xFFFFFFFFu, c, o);
        }
        if (l == 0) { ss[0] = a; sq[0] = c; }
    }
    __syncthreads();
    float mean = ss[0] * (1.f / HIDDEN);
    float var  = sq[0] * (1.f / HIDDEN) - mean * mean;
    float inv  = rsqrtf(var + LN_EPS);
    float o0 = (v0 - mean) * inv * lng[t] + lnb[t];
    float o1 = (v1 - mean) * inv * lng[t + 256] + lnb[t + 256];
    size_t base = (size_t)r * HIDDEN;
    __nv_bfloat16 h0 = __float2bfloat16(o0);
    __nv_bfloat16 h1 = __float2bfloat16(o1);
    g_xn_hi[base + t] = h0;
    g_xn_lo[base + t] = __float2bfloat16(o0 - __bfloat162float(h0));
    g_xn_hi[base + t + 256] = h1;
    g_xn_lo[base + t + 256] = __float2bfloat16(o1 - __bfloat162float(h1));
}

// ---------------- attention: q,k,v fp32 -> ctx hi/lo ----------------
__global__ __launch_bounds__(256) void attn_kernel()
{
    __shared__ float q_s[NUM_SUBNETS][520];
    __shared__ float k_s[NUM_SUBNETS][520];
    __shared__ float sc[HEADS][NUM_SUBNETS][NUM_SUBNETS];

    int b = blockIdx.x;
    int tid = threadIdx.x;

    for (int i = tid; i < NUM_SUBNETS * HIDDEN; i += 256) {
        int m = i >> 9, c = i & 511;
        size_t gi = ((size_t)(m * BATCH + b)) * HIDDEN + c;
        q_s[m][c] = g_q[gi];
        k_s[m][c] = g_k[gi];
    }
    __syncthreads();

    int h = tid >> 5, l = tid & 31;

    #pragma unroll
    for (int pp = 0; pp < 2; pp++) {
        int p = l + pp * 32;
        int m = p >> 3, n = p & 7;
        const float* qp = &q_s[m][h * HEAD_DIM];
        const float* kp = &k_s[n][h * HEAD_DIM];
        float sv = 0.f;
        #pragma unroll
        for (int d = 0; d < HEAD_DIM; d++) sv += qp[d] * kp[d];
        sv *= 0.125f;
        sc[h][m][n] = (m == n) ? 0.f : sv;
    }
    __syncwarp();

    if (l < NUM_SUBNETS) {
        float mx = -1e30f;
        #pragma unroll
        for (int n = 0; n < 8; n++) mx = fmaxf(mx, sc[h][l][n]);
        float e[8], sum = 0.f;
        #pragma unroll
        for (int n = 0; n < 8; n++) { e[n] = expf(sc[h][l][n] - mx); sum += e[n]; }
        float inv = 1.f / sum;
        #pragma unroll
        for (int n = 0; n < 8; n++) sc[h][l][n] = e[n] * inv;
    }
    __syncwarp();

    #pragma unroll
    for (int dd = 0; dd < 2; dd++) {
        int d = l + dd * 32;
        float vv[8];
        #pragma unroll
        for (int n = 0; n < 8; n++)
            vv[n] = g_v[((size_t)(n * BATCH + b)) * HIDDEN + h * HEAD_DIM + d];
        #pragma unroll
        for (int m = 0; m < 8; m++) {
            float cv = 0.f;
            #pragma unroll
            for (int n = 0; n < 8; n++) cv += sc[h][m][n] * vv[n];
            size_t off = ((size_t)(m * BATCH + b)) * HIDDEN + h * HEAD_DIM + d;
            __nv_bfloat16 hi = __float2bfloat16(cv);
            g_ctx_hi[off] = hi;
            g_ctx_lo[off] = __float2bfloat16(cv - __bfloat162float(hi));
        }
    }
}

// ---------------- launch ----------------
extern "C" void kernel_launch(void* const* d_in, const int* in_sizes, int n_in,
                              void* d_out, int out_size)
{
    (void)in_sizes; (void)n_in; (void)out_size;
    const float* x    = (const float*)d_in[0];
    const float* W1   = (const float*)d_in[2];
    const float* b1   = (const float*)d_in[3];
    const float* W2   = (const float*)d_in[4];
    const float* b2   = (const float*)d_in[5];
    const float* ln_g = (const float*)d_in[6];
    const float* ln_b = (const float*)d_in[7];
    const float* Wq   = (const float*)d_in[8];
    const float* bq   = (const float*)d_in[9];
    const float* Wk   = (const float*)d_in[10];
    const float* bk   = (const float*)d_in[11];
    const float* Wv   = (const float*)d_in[12];
    const float* bv   = (const float*)d_in[13];
    const float* Wo   = (const float*)d_in[14];
    const float* bo   = (const float*)d_in[15];
    const float* Wp   = (const float*)d_in[16];
    const float* bp   = (const float*)d_in[17];
    float* out = (float*)d_out;

    __nv_bfloat16 *flat_hi, *flat_lo, *W1T_hi, *W1T_lo, *W2T_hi, *W2T_lo;
    __nv_bfloat16 *WqkvT_hi, *WqkvT_lo, *WoT_hi, *WoT_lo, *WpT_hi, *WpT_lo;
    __nv_bfloat16 *h_hi, *h_lo, *xn_hi, *xn_lo, *ctx_hi, *ctx_lo, *t_hi, *t_lo;
    float *xsub, *pq, *pk, *pv;
    cudaGetSymbolAddress((void**)&flat_hi, g_flat_hi);
    cudaGetSymbolAddress((void**)&flat_lo, g_flat_lo);
    cudaGetSymbolAddress((void**)&W1T_hi,  g_W1T_hi);
    cudaGetSymbolAddress((void**)&W1T_lo,  g_W1T_lo);
    cudaGetSymbolAddress((void**)&W2T_hi,  g_W2T_hi);
    cudaGetSymbolAddress((void**)&W2T_lo,  g_W2T_lo);
    cudaGetSymbolAddress((void**)&WqkvT_hi, g_WqkvT_hi);
    cudaGetSymbolAddress((void**)&WqkvT_lo, g_WqkvT_lo);
    cudaGetSymbolAddress((void**)&WoT_hi,  g_WoT_hi);
    cudaGetSymbolAddress((void**)&WoT_lo,  g_WoT_lo);
    cudaGetSymbolAddress((void**)&WpT_hi,  g_WpT_hi);
    cudaGetSymbolAddress((void**)&WpT_lo,  g_WpT_lo);
    cudaGetSymbolAddress((void**)&h_hi,    g_h_hi);
    cudaGetSymbolAddress((void**)&h_lo,    g_h_lo);
    cudaGetSymbolAddress((void**)&xn_hi,   g_xn_hi);
    cudaGetSymbolAddress((void**)&xn_lo,   g_xn_lo);
    cudaGetSymbolAddress((void**)&ctx_hi,  g_ctx_hi);
    cudaGetSymbolAddress((void**)&ctx_lo,  g_ctx_lo);
    cudaGetSymbolAddress((void**)&t_hi,    g_t_hi);
    cudaGetSymbolAddress((void**)&t_lo,    g_t_lo);
    cudaGetSymbolAddress((void**)&xsub,    g_xsub);
    cudaGetSymbolAddress((void**)&pq,      g_q);
    cudaGetSymbolAddress((void**)&pk,      g_k);
    cudaGetSymbolAddress((void**)&pv,      g_v);

    cudaFuncSetAttribute(tc_gemm<0>, cudaFuncAttributeMaxDynamicSharedMemorySize, GEMM_SMEM);
    cudaFuncSetAttribute(tc_gemm<1>, cudaFuncAttributeMaxDynamicSharedMemorySize, GEMM_SMEM);
    cudaFuncSetAttribute(tc_gemm<2>, cudaFuncAttributeMaxDynamicSharedMemorySize, GEMM_SMEM);
    cudaFuncSetAttribute(tc_gemm<3>, cudaFuncAttributeMaxDynamicSharedMemorySize, GEMM_SMEM);
    cudaFuncSetAttribute(tc_gemm<4>, cudaFuncAttributeMaxDynamicSharedMemorySize, GEMM_SMEM);

    // ---- input conversions ----
    int nExtract = ROWS * KPAD1;
    extract_kernel<<<(nExtract + 255) / 256, 256>>>(x);
    wconv_kernel<<<dim3(KPAD1 / 32, HIDDEN / 32, NUM_SUBNETS), dim3(32, 8)>>>(W1, W1T_hi, W1T_lo, FLAT, HIDDEN, KPAD1);
    wconv_kernel<<<dim3(HIDDEN / 32, HIDDEN / 32, NUM_SUBNETS), dim3(32, 8)>>>(W2, W2T_hi, W2T_lo, HIDDEN, HIDDEN, HIDDEN);
    wconv_kernel<<<dim3(16, 16, 1), dim3(32, 8)>>>(Wq, WqkvT_hi,              WqkvT_lo,              HIDDEN, HIDDEN, HIDDEN);
    wconv_kernel<<<dim3(16, 16, 1), dim3(32, 8)>>>(Wk, WqkvT_hi + 512 * 512,  WqkvT_lo + 512 * 512,  HIDDEN, HIDDEN, HIDDEN);
    wconv_kernel<<<dim3(16, 16, 1), dim3(32, 8)>>>(Wv, WqkvT_hi + 1024 * 512, WqkvT_lo + 1024 * 512, HIDDEN, HIDDEN, HIDDEN);
    wconv_kernel<<<dim3(16, 16, 1), dim3(32, 8)>>>(Wo, WoT_hi, WoT_lo, HIDDEN, HIDDEN, HIDDEN);
    wconv_kernel<<<dim3(16, 16, 1), dim3(32, 8)>>>(Wp, WpT_hi, WpT_lo, HIDDEN, HIDDEN, HIDDEN);

    dim3 g512(HIDDEN / BN, ROWS / BM);        // 8 x 16 = 128 CTAs
    dim3 gqkv(3 * HIDDEN / BN, ROWS / BM);    // 24 x 16 = 384 CTAs

    // GEMM1: h = relu(flat @ W1 + b1)
    tc_gemm<0><<<g512, 256, GEMM_SMEM>>>(flat_hi, flat_lo, KPAD1, W1T_hi, W1T_lo, KPAD1,
        (long)HIDDEN * KPAD1, KPAD1 / BK, b1, nullptr, h_hi, h_lo,
        nullptr, nullptr, nullptr, nullptr, nullptr, nullptr, nullptr);
    // GEMM2: xsub = h @ W2 + b2
    tc_gemm<1><<<g512, 256, GEMM_SMEM>>>(h_hi, h_lo, HIDDEN, W2T_hi, W2T_lo, HIDDEN,
        (long)HIDDEN * HIDDEN, HIDDEN / BK, b2, xsub, nullptr, nullptr,
        nullptr, nullptr, nullptr, nullptr, nullptr, nullptr, nullptr);
    // LN -> xn hi/lo
    ln_kernel<<<ROWS, 256>>>(ln_g, ln_b);
    // QKV fused
    tc_gemm<2><<<gqkv, 256, GEMM_SMEM>>>(xn_hi, xn_lo, HIDDEN, WqkvT_hi, WqkvT_lo, HIDDEN,
        0L, HIDDEN / BK, nullptr, nullptr, nullptr, nullptr,
        nullptr, pq, pk, pv, bq, bk, bv);
    // attention -> ctx hi/lo
    attn_kernel<<<BATCH, 256>>>();
    // O: t = ctx @ Wo + bo
    tc_gemm<3><<<g512, 256, GEMM_SMEM>>>(ctx_hi, ctx_lo, HIDDEN, WoT_hi, WoT_lo, HIDDEN,
        0L, HIDDEN / BK, bo, nullptr, t_hi, t_lo,
        nullptr, nullptr, nullptr, nullptr, nullptr, nullptr, nullptr);
    // P: out = t @ Wp + bp + xsub (permuted to (b,s))
    tc_gemm<4><<<g512, 256, GEMM_SMEM>>>(t_hi, t_lo, HIDDEN, WpT_hi, WpT_lo, HIDDEN,
        0L, HIDDEN / BK, bp, out, nullptr, nullptr,
        xsub, nullptr, nullptr, nullptr, nullptr, nullptr, nullptr);
}

// round 4
// speedup vs baseline: 3.0072x; 1.0798x over previous
#include <cuda_runtime.h>
#include <cuda_bf16.h>
#include <math.h>
#include <cstdint>

// ---------------- problem constants ----------------
#define NUM_SUBNETS 8
#define REGIONS     50
#define TOTAL_R     400
#define HIDDEN      512
#define HEADS       8
#define HEAD_DIM    64
#define BATCH       256
#define FLAT        2500
#define ROWS        (NUM_SUBNETS * BATCH)   // 2048
#define LN_EPS      1e-5f
#define KPAD1       2560                    // FLAT padded to multiple of 32

// GEMM tiling
#define BM 128
#define BN 64
#define BK 32
#define ASTRIDE 80                          // bytes per 32-col bf16 row (64 + 16 pad)
#define A_BYTES (BM * ASTRIDE)              // 10240
#define B_BYTES (BN * ASTRIDE)              // 5120
#define STAGE   (2 * A_BYTES + 2 * B_BYTES) // 30720
#define NSTAGE  4
#define GEMM_SMEM (NSTAGE * STAGE)          // 122880

typedef unsigned long long u64;

// ---------------- scratch (device globals) ----------------
__device__ __nv_bfloat16 g_flat_hi[ROWS * KPAD1];
__device__ __nv_bfloat16 g_flat_lo[ROWS * KPAD1];
__device__ __nv_bfloat16 g_W1T_hi[NUM_SUBNETS * HIDDEN * KPAD1];
__device__ __nv_bfloat16 g_W1T_lo[NUM_SUBNETS * HIDDEN * KPAD1];
__device__ __nv_bfloat16 g_W2T_hi[NUM_SUBNETS * HIDDEN * HIDDEN];
__device__ __nv_bfloat16 g_W2T_lo[NUM_SUBNETS * HIDDEN * HIDDEN];
__device__ __nv_bfloat16 g_WqkvT_hi[3 * HIDDEN * HIDDEN];
__device__ __nv_bfloat16 g_WqkvT_lo[3 * HIDDEN * HIDDEN];
__device__ __nv_bfloat16 g_WoT_hi[HIDDEN * HIDDEN];
__device__ __nv_bfloat16 g_WoT_lo[HIDDEN * HIDDEN];
__device__ __nv_bfloat16 g_WpT_hi[HIDDEN * HIDDEN];
__device__ __nv_bfloat16 g_WpT_lo[HIDDEN * HIDDEN];

__device__ __nv_bfloat16 g_h_hi[ROWS * HIDDEN];
__device__ __nv_bfloat16 g_h_lo[ROWS * HIDDEN];
__device__ float         g_xsub[ROWS * HIDDEN];
__device__ __nv_bfloat16 g_xn_hi[ROWS * HIDDEN];
__device__ __nv_bfloat16 g_xn_lo[ROWS * HIDDEN];
__device__ float         g_q[ROWS * HIDDEN];
__device__ float         g_k[ROWS * HIDDEN];
__device__ float         g_v[ROWS * HIDDEN];
__device__ __nv_bfloat16 g_ctx_hi[ROWS * HIDDEN];
__device__ __nv_bfloat16 g_ctx_lo[ROWS * HIDDEN];
__device__ __nv_bfloat16 g_t_hi[ROWS * HIDDEN];
__device__ __nv_bfloat16 g_t_lo[ROWS * HIDDEN];

// ---------------- PTX helpers (sm_80-ratified only) ----------------
__device__ __forceinline__ uint32_t smem_u32(const void* p) {
    uint32_t a;
    asm("{ .reg .u64 t; cvta.to.shared.u64 t, %1; cvt.u32.u64 %0, t; }" : "=r"(a) : "l"(p));
    return a;
}
__device__ __forceinline__ void cpa16(uint32_t s, const void* g) {
    asm volatile("cp.async.cg.shared.global [%0], [%1], 16;" :: "r"(s), "l"(g));
}
__device__ __forceinline__ void cpa_commit() {
    asm volatile("cp.async.commit_group;" ::: "memory");
}
template<int N> __device__ __forceinline__ void cpa_wait() {
    asm volatile("cp.async.wait_group %0;" :: "n"(N) : "memory");
}
__device__ __forceinline__ void ldm4(uint32_t a, uint32_t* r) {
    asm volatile("ldmatrix.sync.aligned.m8n8.x4.shared.b16 {%0,%1,%2,%3}, [%4];"
        : "=r"(r[0]), "=r"(r[1]), "=r"(r[2]), "=r"(r[3]) : "r"(a));
}
__device__ __forceinline__ void mma16816(float* c, const uint32_t* a, uint32_t b0, uint32_t b1) {
    asm volatile("mma.sync.aligned.m16n8k16.row.col.f32.bf16.bf16.f32 "
        "{%0,%1,%2,%3},{%4,%5,%6,%7},{%8,%9},{%0,%1,%2,%3};"
        : "+f"(c[0]), "+f"(c[1]), "+f"(c[2]), "+f"(c[3])
        : "r"(a[0]), "r"(a[1]), "r"(a[2]), "r"(a[3]), "r"(b0), "r"(b1));
}

__device__ __forceinline__ void store_hilo(__nv_bfloat16* hi, __nv_bfloat16* lo,
                                           size_t off, float v0, float v1) {
    __nv_bfloat16 h0 = __float2bfloat16(v0);
    __nv_bfloat16 h1 = __float2bfloat16(v1);
    __nv_bfloat16 l0 = __float2bfloat16(v0 - __bfloat162float(h0));
    __nv_bfloat16 l1 = __float2bfloat16(v1 - __bfloat162float(h1));
    __nv_bfloat162 hp; hp.x = h0; hp.y = h1;
    __nv_bfloat162 lp; lp.x = l0; lp.y = l1;
    *(__nv_bfloat162*)(hi + off) = hp;
    *(__nv_bfloat162*)(lo + off) = lp;
}

union BF4 { uint2 u; __nv_bfloat162 p[2]; };

__device__ __forceinline__ void split4(const float* v, BF4& hv, BF4& lv) {
    __nv_bfloat16 h0 = __float2bfloat16(v[0]);
    __nv_bfloat16 h1 = __float2bfloat16(v[1]);
    __nv_bfloat16 h2 = __float2bfloat16(v[2]);
    __nv_bfloat16 h3 = __float2bfloat16(v[3]);
    hv.p[0].x = h0; hv.p[0].y = h1; hv.p[1].x = h2; hv.p[1].y = h3;
    lv.p[0].x = __float2bfloat16(v[0] - __bfloat162float(h0));
    lv.p[0].y = __float2bfloat16(v[1] - __bfloat162float(h1));
    lv.p[1].x = __float2bfloat16(v[2] - __bfloat162float(h2));
    lv.p[1].y = __float2bfloat16(v[3] - __bfloat162float(h3));
}

// ---------------- kernel: extract diagonal blocks -> bf16 hi/lo (4 elems/thread) ----------------
__global__ void extract_kernel(const float* __restrict__ x) {
    int q = blockIdx.x * blockDim.x + threadIdx.x;        // quad index
    if (q >= ROWS * KPAD1 / 4) return;
    int f0 = (q % (KPAD1 / 4)) * 4;
    int sb = q / (KPAD1 / 4);
    int b  = sb & (BATCH - 1);
    int s  = sb >> 8;
    const float* xb = x + (size_t)b * (TOTAL_R * TOTAL_R);
    float v[4];
    #pragma unroll
    for (int e = 0; e < 4; e++) {
        int f = f0 + e;
        float vv = 0.f;
        if (f < FLAT) {
            int i = f / REGIONS;
            int j = f - i * REGIONS;
            vv = xb[(s * REGIONS + i) * TOTAL_R + (s * REGIONS + j)];
        }
        v[e] = vv;
    }
    BF4 hv, lv; split4(v, hv, lv);
    size_t off = (size_t)sb * KPAD1 + f0;
    *(uint2*)(g_flat_hi + off) = hv.u;
    *(uint2*)(g_flat_lo + off) = lv.u;
}

// ---------------- W1 transpose+split: [s][2500][512] -> [s][512][2560] ----------------
__global__ void wconv_w1_kernel(const float* __restrict__ src) {
    __shared__ float tile[32][33];
    int k0 = blockIdx.x * 32, n0 = blockIdx.y * 32, z = blockIdx.z;
    const float* sp = src + (size_t)z * FLAT * HIDDEN;
    size_t dbase = (size_t)z * HIDDEN * KPAD1;
    int tid = threadIdx.x;
    int tx = tid & 31, ty = tid >> 5;       // 256 threads
    #pragma unroll
    for (int r = 0; r < 4; r++) {
        int k = k0 + ty + r * 8;
        tile[ty + r * 8][tx] = (k < FLAT) ? sp[(size_t)k * HIDDEN + n0 + tx] : 0.f;
    }
    __syncthreads();
    int n = tid >> 3, kq = (tid & 7) * 4;
    float v[4];
    #pragma unroll
    for (int i = 0; i < 4; i++) v[i] = tile[kq + i][n];
    BF4 hv, lv; split4(v, hv, lv);
    size_t off = dbase + (size_t)(n0 + n) * KPAD1 + k0 + kq;
    *(uint2*)(g_W1T_hi + off) = hv.u;
    *(uint2*)(g_W1T_lo + off) = lv.u;
}

// ---------------- batched 512x512 transpose+split (13 slices, one launch) ----------------
struct W13 {
    const float* src[13];
    __nv_bfloat16* dhi[13];
    __nv_bfloat16* dlo[13];
};
__global__ void wconv512_kernel(W13 a) {
    __shared__ float tile[32][33];
    int z = blockIdx.z;
    const float* sp = a.src[z];
    __nv_bfloat16* dhi = a.dhi[z];
    __nv_bfloat16* dlo = a.dlo[z];
    int k0 = blockIdx.x * 32, n0 = blockIdx.y * 32;
    int tid = threadIdx.x;
    int tx = tid & 31, ty = tid >> 5;
    #pragma unroll
    for (int r = 0; r < 4; r++) {
        int k = k0 + ty + r * 8;
        tile[ty + r * 8][tx] = sp[(size_t)k * HIDDEN + n0 + tx];
    }
    __syncthreads();
    int n = tid >> 3, kq = (tid & 7) * 4;
    float v[4];
    #pragma unroll
    for (int i = 0; i < 4; i++) v[i] = tile[kq + i][n];
    BF4 hv, lv; split4(v, hv, lv);
    size_t off = (size_t)(n0 + n) * HIDDEN + k0 + kq;
    *(uint2*)(dhi + off) = hv.u;
    *(uint2*)(dlo + off) = lv.u;
}

// ---------------- mma.sync GEMM: C[2048][N] = A[2048][K] * W^T + epilogue ----------------
// C = Ah*Bh + Ah*Bl + Al*Bh, fp32 accum. 4-buffer / 3-deep cp.async pipeline.
// EP: 0 relu->hi/lo | 1 f32 | 2 qkv split f32 | 3 hi/lo | 4 resid+permute f32
template<int EP>
__global__ __launch_bounds__(256) void tc_gemm(
    const __nv_bfloat16* __restrict__ Ahi, const __nv_bfloat16* __restrict__ Alo, int sA,
    const __nv_bfloat16* __restrict__ Bhi, const __nv_bfloat16* __restrict__ Blo, int sB,
    long bSub, int Ksteps,
    const float* __restrict__ bias,
    float* __restrict__ o32,
    __nv_bfloat16* __restrict__ oHi, __nv_bfloat16* __restrict__ oLo,
    const float* __restrict__ resid,
    float* __restrict__ oq, float* __restrict__ okk, float* __restrict__ ov,
    const float* __restrict__ bq, const float* __restrict__ bk, const float* __restrict__ bv)
{
    extern __shared__ __align__(128) char smem[];
    const uint32_t sbase = smem_u32(smem);
    const int tid = threadIdx.x;
    const int mBase = blockIdx.y * BM;
    const int nBase = blockIdx.x * BN;
    const int sIdx = blockIdx.y >> 1;        // 2 M-tiles (256 rows) per subnet

    const __nv_bfloat16* aH = Ahi + (size_t)mBase * sA;
    const __nv_bfloat16* aL = Alo + (size_t)mBase * sA;
    size_t boff = (bSub > 0 ? (size_t)sIdx * (size_t)bSub : 0) + (size_t)nBase * sB;
    const __nv_bfloat16* bH = Bhi + boff;
    const __nv_bfloat16* bL = Blo + boff;
    const float* biasP = bias ? (bias + (bSub > 0 ? sIdx * HIDDEN : 0)) : bias;

    // ---- async-copy one K-chunk; ALWAYS commits exactly one group ----
    auto issue = [&](int chunk) {
        if (chunk < Ksteps) {
            const uint32_t st = sbase + (chunk & (NSTAGE - 1)) * STAGE;
            const int k0 = chunk * BK;
            #pragma unroll
            for (int i = 0; i < 2; i++) {                 // A: 128 rows x 4 chunks of 16B
                int idx = tid + i * 256;
                int row = idx >> 2, c = idx & 3;
                uint32_t so = st + row * ASTRIDE + c * 16;
                cpa16(so,           aH + (size_t)row * sA + k0 + c * 8);
                cpa16(so + A_BYTES, aL + (size_t)row * sA + k0 + c * 8);
            }
            {                                             // B: 64 rows x 4 chunks
                int row = tid >> 2, c = tid & 3;
                uint32_t so = st + 2 * A_BYTES + row * ASTRIDE + c * 16;
                cpa16(so,           bH + (size_t)row * sB + k0 + c * 8);
                cpa16(so + B_BYTES, bL + (size_t)row * sB + k0 + c * 8);
            }
        }
        cpa_commit();
    };

    issue(0); issue(1); issue(2);

    const int wid = tid >> 5, lane = tid & 31;
    const int wm = wid >> 1, wn = wid & 1;            // 4 x 2 warps, warp tile 32x32
    const uint32_t lrow = lane & 15;
    const uint32_t lcol = (lane >> 4) * 16;

    float acc[2][4][4];
    #pragma unroll
    for (int i = 0; i < 2; i++)
        #pragma unroll
        for (int j = 0; j < 4; j++)
            #pragma unroll
            for (int t = 0; t < 4; t++) acc[i][j][t] = 0.f;

    for (int s = 0; s < Ksteps; ++s) {
        cpa_wait<2>();                 // stage s landed (one commit per issue, incl. empties)
        __syncthreads();               // all warps done with buffer (s-1)&3
        issue(s + 3);                  // overwrites buffer (s-1)&3, overlaps compute below
        const uint32_t st = sbase + (s & (NSTAGE - 1)) * STAGE;
        #pragma unroll
        for (int kk = 0; kk < 2; ++kk) {
            uint32_t aHf[2][4], aLf[2][4], bHf[2][4], bLf[2][4];
            #pragma unroll
            for (int am = 0; am < 2; am++) {
                uint32_t ad = st + (wm * 32 + am * 16 + lrow) * ASTRIDE + kk * 32 + lcol;
                ldm4(ad,           aHf[am]);
                ldm4(ad + A_BYTES, aLf[am]);
            }
            #pragma unroll
            for (int j = 0; j < 2; j++) {
                uint32_t bd = st + 2 * A_BYTES + (wn * 32 + j * 16 + lrow) * ASTRIDE + kk * 32 + lcol;
                ldm4(bd,           bHf[j]);
                ldm4(bd + B_BYTES, bLf[j]);
            }
            #pragma unroll
            for (int am = 0; am < 2; am++) {
                #pragma unroll
                for (int j = 0; j < 2; j++) {
                    mma16816(acc[am][2*j],   aHf[am], bHf[j][0], bHf[j][2]);
                    mma16816(acc[am][2*j+1], aHf[am], bHf[j][1], bHf[j][3]);
                    mma16816(acc[am][2*j],   aHf[am], bLf[j][0], bLf[j][2]);
                    mma16816(acc[am][2*j+1], aHf[am], bLf[j][1], bLf[j][3]);
                    mma16816(acc[am][2*j],   aLf[am], bHf[j][0], bHf[j][2]);
                    mma16816(acc[am][2*j+1], aLf[am], bHf[j][1], bHf[j][3]);
                }
            }
        }
    }

    // ---- epilogue: registers -> global ----
    #pragma unroll
    for (int am = 0; am < 2; am++) {
        #pragma unroll
        for (int an = 0; an < 4; an++) {
            int m0 = mBase + wm * 32 + am * 16 + (lane >> 2);
            int g  = nBase + wn * 32 + an * 8 + (lane & 3) * 2;
            #pragma unroll
            for (int half = 0; half < 2; half++) {
                int m = m0 + half * 8;
                float v0 = acc[am][an][half * 2];
                float v1 = acc[am][an][half * 2 + 1];
                if (EP == 0) {                          // relu -> h hi/lo
                    v0 = fmaxf(v0 + biasP[g], 0.f);
                    v1 = fmaxf(v1 + biasP[g + 1], 0.f);
                    store_hilo(oHi, oLo, (size_t)m * HIDDEN + g, v0, v1);
                } else if (EP == 1) {                   // xsub fp32
                    v0 += biasP[g]; v1 += biasP[g + 1];
                    *(float2*)(o32 + (size_t)m * HIDDEN + g) = make_float2(v0, v1);
                } else if (EP == 2) {                   // qkv fp32 split
                    int which = g >> 9, lc = g & 511;
                    const float* bb = (which == 0) ? bq : (which == 1) ? bk : bv;
                    float* dst = (which == 0) ? oq : (which == 1) ? okk : ov;
                    v0 += bb[lc]; v1 += bb[lc + 1];
                    *(float2*)(dst + (size_t)m * HIDDEN + lc) = make_float2(v0, v1);
                } else if (EP == 3) {                   // t hi/lo
                    v0 += biasP[g]; v1 += biasP[g + 1];
                    store_hilo(oHi, oLo, (size_t)m * HIDDEN + g, v0, v1);
                } else {                                // out = . + bp + xsub, (b,s) order
                    v0 += biasP[g] + resid[(size_t)m * HIDDEN + g];
                    v1 += biasP[g + 1] + resid[(size_t)m * HIDDEN + g + 1];
                    int bb2 = m & (BATCH - 1), ss = m >> 8;
                    *(float2*)(o32 + ((size_t)((bb2 << 3) + ss)) * HIDDEN + g) = make_float2(v0, v1);
                }
            }
        }
    }
}

// ---------------- LayerNorm: xsub fp32 -> xn hi/lo ----------------
__global__ __launch_bounds__(256) void ln_kernel(const float* __restrict__ lng,
                                                 const float* __restrict__ lnb)
{
    int r = blockIdx.x, t = threadIdx.x;
    const float* xs = g_xsub + (size_t)r * HIDDEN;
    float v0 = xs[t], v1 = xs[t + 256];
    float s = v0 + v1, q = v0 * v0 + v1 * v1;
    #pragma unroll
    for (int o = 16; o > 0; o >>= 1) {
        s += __shfl_xor_sync(0xFFFFFFFFu, s, o);
        q += __shfl_xor_sync(0xFFFFFFFFu, q, o);
    }
    __shared__ float ss[8], sq[8];
    int w = t >> 5, l = t & 31;
    if (l == 0) { ss[w] = s; sq[w] = q; }
    __syncthreads();
    if (w == 0) {
        float a = (l < 8) ? ss[l] : 0.f;
        float c = (l < 8) ? sq[l] : 0.f;
        #pragma unroll
        for (int o = 4; o > 0; o >>= 1) {
            a += __shfl_xor_sync(0xFFFFFFFFu, a, o);
            c += __shfl_xor_sync(0xFFFFFFFFu, c, o);
        }
        if (l == 0) { ss[0] = a; sq[0] = c; }
    }
    __syncthreads();
    float mean = ss[0] * (1.f / HIDDEN);
    float var  = sq[0] * (1.f / HIDDEN) - mean * mean;
    float inv  = rsqrtf(var + LN_EPS);
    float o0 = (v0 - mean) * inv * lng[t] + lnb[t];
    float o1 = (v1 - mean) * inv * lng[t + 256] + lnb[t + 256];
    size_t base = (size_t)r * HIDDEN;
    __nv_bfloat16 h0 = __float2bfloat16(o0);
    __nv_bfloat16 h1 = __float2bfloat16(o1);
    g_xn_hi[base + t] = h0;
    g_xn_lo[base + t] = __float2bfloat16(o0 - __bfloat162float(h0));
    g_xn_hi[base + t + 256] = h1;
    g_xn_lo[base + t + 256] = __float2bfloat16(o1 - __bfloat162float(h1));
}

// ---------------- attention: q,k,v fp32 -> ctx hi/lo ----------------
__global__ __launch_bounds__(256) void attn_kernel()
{
    __shared__ float q_s[NUM_SUBNETS][520];
    __shared__ float k_s[NUM_SUBNETS][520];
    __shared__ float sc[HEADS][NUM_SUBNETS][NUM_SUBNETS];

    int b = blockIdx.x;
    int tid = threadIdx.x;

    for (int i = tid; i < NUM_SUBNETS * HIDDEN; i += 256) {
        int m = i >> 9, c = i & 511;
        size_t gi = ((size_t)(m * BATCH + b)) * HIDDEN + c;
        q_s[m][c] = g_q[gi];
        k_s[m][c] = g_k[gi];
    }
    __syncthreads();

    int h = tid >> 5, l = tid & 31;

    #pragma unroll
    for (int pp = 0; pp < 2; pp++) {
        int p = l + pp * 32;
        int m = p >> 3, n = p & 7;
        const float* qp = &q_s[m][h * HEAD_DIM];
        const float* kp = &k_s[n][h * HEAD_DIM];
        float sv = 0.f;
        #pragma unroll
        for (int d = 0; d < HEAD_DIM; d++) sv += qp[d] * kp[d];
        sv *= 0.125f;
        sc[h][m][n] = (m == n) ? 0.f : sv;
    }
    __syncwarp();

    if (l < NUM_SUBNETS) {
        float mx = -1e30f;
        #pragma unroll
        for (int n = 0; n < 8; n++) mx = fmaxf(mx, sc[h][l][n]);
        float e[8], sum = 0.f;
        #pragma unroll
        for (int n = 0; n < 8; n++) { e[n] = expf(sc[h][l][n] - mx); sum += e[n]; }
        float inv = 1.f / sum;
        #pragma unroll
        for (int n = 0; n < 8; n++) sc[h][l][n] = e[n] * inv;
    }
    __syncwarp();

    #pragma unroll
    for (int dd = 0; dd < 2; dd++) {
        int d = l + dd * 32;
        float vv[8];
        #pragma unroll
        for (int n = 0; n < 8; n++)
            vv[n] = g_v[((size_t)(n * BATCH + b)) * HIDDEN + h * HEAD_DIM + d];
        #pragma unroll
        for (int m = 0; m < 8; m++) {
            float cv = 0.f;
            #pragma unroll
            for (int n = 0; n < 8; n++) cv += sc[h][m][n] * vv[n];
            size_t off = ((size_t)(m * BATCH + b)) * HIDDEN + h * HEAD_DIM + d;
            __nv_bfloat16 hi = __float2bfloat16(cv);
            g_ctx_hi[off] = hi;
            g_ctx_lo[off] = __float2bfloat16(cv - __bfloat162float(hi));
        }
    }
}

// ---------------- launch ----------------
extern "C" void kernel_launch(void* const* d_in, const int* in_sizes, int n_in,
                              void* d_out, int out_size)
{
    (void)in_sizes; (void)n_in; (void)out_size;
    const float* x    = (const float*)d_in[0];
    const float* W1   = (const float*)d_in[2];
    const float* b1   = (const float*)d_in[3];
    const float* W2   = (const float*)d_in[4];
    const float* b2   = (const float*)d_in[5];
    const float* ln_g = (const float*)d_in[6];
    const float* ln_b = (const float*)d_in[7];
    const float* Wq   = (const float*)d_in[8];
    const float* bq   = (const float*)d_in[9];
    const float* Wk   = (const float*)d_in[10];
    const float* bk   = (const float*)d_in[11];
    const float* Wv   = (const float*)d_in[12];
    const float* bv   = (const float*)d_in[13];
    const float* Wo   = (const float*)d_in[14];
    const float* bo   = (const float*)d_in[15];
    const float* Wp   = (const float*)d_in[16];
    const float* bp   = (const float*)d_in[17];
    float* out = (float*)d_out;

    __nv_bfloat16 *flat_hi, *flat_lo, *W1T_hi, *W1T_lo, *W2T_hi, *W2T_lo;
    __nv_bfloat16 *WqkvT_hi, *WqkvT_lo, *WoT_hi, *WoT_lo, *WpT_hi, *WpT_lo;
    __nv_bfloat16 *h_hi, *h_lo, *xn_hi, *xn_lo, *ctx_hi, *ctx_lo, *t_hi, *t_lo;
    float *xsub, *pq, *pk, *pv;
    cudaGetSymbolAddress((void**)&flat_hi, g_flat_hi);
    cudaGetSymbolAddress((void**)&flat_lo, g_flat_lo);
    cudaGetSymbolAddress((void**)&W1T_hi,  g_W1T_hi);
    cudaGetSymbolAddress((void**)&W1T_lo,  g_W1T_lo);
    cudaGetSymbolAddress((void**)&W2T_hi,  g_W2T_hi);
    cudaGetSymbolAddress((void**)&W2T_lo,  g_W2T_lo);
    cudaGetSymbolAddress((void**)&WqkvT_hi, g_WqkvT_hi);
    cudaGetSymbolAddress((void**)&WqkvT_lo, g_WqkvT_lo);
    cudaGetSymbolAddress((void**)&WoT_hi,  g_WoT_hi);
    cudaGetSymbolAddress((void**)&WoT_lo,  g_WoT_lo);
    cudaGetSymbolAddress((void**)&WpT_hi,  g_WpT_hi);
    cudaGetSymbolAddress((void**)&WpT_lo,  g_WpT_lo);
    cudaGetSymbolAddress((void**)&h_hi,    g_h_hi);
    cudaGetSymbolAddress((void**)&h_lo,    g_h_lo);
    cudaGetSymbolAddress((void**)&xn_hi,   g_xn_hi);
    cudaGetSymbolAddress((void**)&xn_lo,   g_xn_lo);
    cudaGetSymbolAddress((void**)&ctx_hi,  g_ctx_hi);
    cudaGetSymbolAddress((void**)&ctx_lo,  g_ctx_lo);
    cudaGetSymbolAddress((void**)&t_hi,    g_t_hi);
    cudaGetSymbolAddress((void**)&t_lo,    g_t_lo);
    cudaGetSymbolAddress((void**)&xsub,    g_xsub);
    cudaGetSymbolAddress((void**)&pq,      g_q);
    cudaGetSymbolAddress((void**)&pk,      g_k);
    cudaGetSymbolAddress((void**)&pv,      g_v);

    cudaFuncSetAttribute(tc_gemm<0>, cudaFuncAttributeMaxDynamicSharedMemorySize, GEMM_SMEM);
    cudaFuncSetAttribute(tc_gemm<1>, cudaFuncAttributeMaxDynamicSharedMemorySize, GEMM_SMEM);
    cudaFuncSetAttribute(tc_gemm<2>, cudaFuncAttributeMaxDynamicSharedMemorySize, GEMM_SMEM);
    cudaFuncSetAttribute(tc_gemm<3>, cudaFuncAttributeMaxDynamicSharedMemorySize, GEMM_SMEM);
    cudaFuncSetAttribute(tc_gemm<4>, cudaFuncAttributeMaxDynamicSharedMemorySize, GEMM_SMEM);

    // ---- input conversions ----
    extract_kernel<<<(ROWS * KPAD1 / 4 + 255) / 256, 256>>>(x);
    wconv_w1_kernel<<<dim3(KPAD1 / 32, HIDDEN / 32, NUM_SUBNETS), 256>>>(W1);

    W13 wa;
    for (int z = 0; z < 8; z++) {
        wa.src[z] = W2 + (size_t)z * HIDDEN * HIDDEN;
        wa.dhi[z] = W2T_hi + (size_t)z * HIDDEN * HIDDEN;
        wa.dlo[z] = W2T_lo + (size_t)z * HIDDEN * HIDDEN;
    }
    const float* srcs[5] = { Wq, Wk, Wv, Wo, Wp };
    __nv_bfloat16* dhis[5] = { WqkvT_hi, WqkvT_hi + 512 * 512, WqkvT_hi + 1024 * 512, WoT_hi, WpT_hi };
    __nv_bfloat16* dlos[5] = { WqkvT_lo, WqkvT_lo + 512 * 512, WqkvT_lo + 1024 * 512, WoT_lo, WpT_lo };
    for (int z = 0; z < 5; z++) {
        wa.src[8 + z] = srcs[z];
        wa.dhi[8 + z] = dhis[z];
        wa.dlo[8 + z] = dlos[z];
    }
    wconv512_kernel<<<dim3(16, 16, 13), 256>>>(wa);

    dim3 g512(HIDDEN / BN, ROWS / BM);        // 8 x 16 = 128 CTAs
    dim3 gqkv(3 * HIDDEN / BN, ROWS / BM);    // 24 x 16 = 384 CTAs

    // GEMM1: h = relu(flat @ W1 + b1)
    tc_gemm<0><<<g512, 256, GEMM_SMEM>>>(flat_hi, flat_lo, KPAD1, W1T_hi, W1T_lo, KPAD1,
        (long)HIDDEN * KPAD1, KPAD1 / BK, b1, nullptr, h_hi, h_lo,
        nullptr, nullptr, nullptr, nullptr, nullptr, nullptr, nullptr);
    // GEMM2: xsub = h @ W2 + b2
    tc_gemm<1><<<g512, 256, GEMM_SMEM>>>(h_hi, h_lo, HIDDEN, W2T_hi, W2T_lo, HIDDEN,
        (long)HIDDEN * HIDDEN, HIDDEN / BK, b2, xsub, nullptr, nullptr,
        nullptr, nullptr, nullptr, nullptr, nullptr, nullptr, nullptr);
    // LN -> xn hi/lo
    ln_kernel<<<ROWS, 256>>>(ln_g, ln_b);
    // QKV fused
    tc_gemm<2><<<gqkv, 256, GEMM_SMEM>>>(xn_hi, xn_lo, HIDDEN, WqkvT_hi, WqkvT_lo, HIDDEN,
        0L, HIDDEN / BK, nullptr, nullptr, nullptr, nullptr,
        nullptr, pq, pk, pv, bq, bk, bv);
    // attention -> ctx hi/lo
    attn_kernel<<<BATCH, 256>>>();
    // O: t = ctx @ Wo + bo
    tc_gemm<3><<<g512, 256, GEMM_SMEM>>>(ctx_hi, ctx_lo, HIDDEN, WoT_hi, WoT_lo, HIDDEN,
        0L, HIDDEN / BK, bo, nullptr, t_hi, t_lo,
        nullptr, nullptr, nullptr, nullptr, nullptr, nullptr, nullptr);
    // P: out = t @ Wp + bp + xsub (permuted to (b,s))
    tc_gemm<4><<<g512, 256, GEMM_SMEM>>>(t_hi, t_lo, HIDDEN, WpT_hi, WpT_lo, HIDDEN,
        0L, HIDDEN / BK, bp, out, nullptr, nullptr,
        xsub, nullptr, nullptr, nullptr, nullptr, nullptr, nullptr);
}

// round 5
// speedup vs baseline: 3.3444x; 1.1121x over previous
#include <cuda_runtime.h>
#include <cuda_bf16.h>
#include <math.h>
#include <cstdint>

// ---------------- problem constants ----------------
#define NUM_SUBNETS 8
#define REGIONS     50
#define TOTAL_R     400
#define HIDDEN      512
#define HEADS       8
#define HEAD_DIM    64
#define BATCH       256
#define FLAT        2500
#define ROWS        (NUM_SUBNETS * BATCH)   // 2048
#define LN_EPS      1e-5f
#define KPAD1       2560                    // FLAT padded to multiple of 64

// GEMM tiling
#define BM 64
#define BN 64
#define BK 64
#define ASTRIDE 144                         // bytes per 64-col bf16 row (128 + 16 pad)
#define T_BYTES (BM * ASTRIDE)              // 9216 per tile array
#define STAGE   (4 * T_BYTES)               // 36864 (Ahi,Alo,Bhi,Blo)
#define NSTAGE  3
#define GEMM_SMEM (NSTAGE * STAGE)          // 110592 -> 2 CTAs/SM

typedef unsigned long long u64;

// ---------------- scratch (device globals) ----------------
__device__ __nv_bfloat16 g_flat_hi[ROWS * KPAD1];
__device__ __nv_bfloat16 g_flat_lo[ROWS * KPAD1];
__device__ __nv_bfloat16 g_W1T_hi[NUM_SUBNETS * HIDDEN * KPAD1];
__device__ __nv_bfloat16 g_W1T_lo[NUM_SUBNETS * HIDDEN * KPAD1];
__device__ __nv_bfloat16 g_W2T_hi[NUM_SUBNETS * HIDDEN * HIDDEN];
__device__ __nv_bfloat16 g_W2T_lo[NUM_SUBNETS * HIDDEN * HIDDEN];
__device__ __nv_bfloat16 g_WqkvT_hi[3 * HIDDEN * HIDDEN];
__device__ __nv_bfloat16 g_WqkvT_lo[3 * HIDDEN * HIDDEN];
__device__ __nv_bfloat16 g_WoT_hi[HIDDEN * HIDDEN];
__device__ __nv_bfloat16 g_WoT_lo[HIDDEN * HIDDEN];
__device__ __nv_bfloat16 g_WpT_hi[HIDDEN * HIDDEN];
__device__ __nv_bfloat16 g_WpT_lo[HIDDEN * HIDDEN];

__device__ __nv_bfloat16 g_h_hi[ROWS * HIDDEN];
__device__ __nv_bfloat16 g_h_lo[ROWS * HIDDEN];
__device__ float         g_xsub[ROWS * HIDDEN];
__device__ __nv_bfloat16 g_xn_hi[ROWS * HIDDEN];
__device__ __nv_bfloat16 g_xn_lo[ROWS * HIDDEN];
__device__ float         g_q[ROWS * HIDDEN];
__device__ float         g_k[ROWS * HIDDEN];
__device__ float         g_v[ROWS * HIDDEN];
__device__ __nv_bfloat16 g_ctx_hi[ROWS * HIDDEN];
__device__ __nv_bfloat16 g_ctx_lo[ROWS * HIDDEN];
__device__ __nv_bfloat16 g_t_hi[ROWS * HIDDEN];
__device__ __nv_bfloat16 g_t_lo[ROWS * HIDDEN];

// ---------------- PTX helpers (sm_80-ratified only) ----------------
__device__ __forceinline__ uint32_t smem_u32(const void* p) {
    uint32_t a;
    asm("{ .reg .u64 t; cvta.to.shared.u64 t, %1; cvt.u32.u64 %0, t; }" : "=r"(a) : "l"(p));
    return a;
}
__device__ __forceinline__ void cpa16(uint32_t s, const void* g) {
    asm volatile("cp.async.cg.shared.global [%0], [%1], 16;" :: "r"(s), "l"(g));
}
__device__ __forceinline__ void cpa_commit() {
    asm volatile("cp.async.commit_group;" ::: "memory");
}
template<int N> __device__ __forceinline__ void cpa_wait() {
    asm volatile("cp.async.wait_group %0;" :: "n"(N) : "memory");
}
__device__ __forceinline__ void ldm4(uint32_t a, uint32_t* r) {
    asm volatile("ldmatrix.sync.aligned.m8n8.x4.shared.b16 {%0,%1,%2,%3}, [%4];"
        : "=r"(r[0]), "=r"(r[1]), "=r"(r[2]), "=r"(r[3]) : "r"(a));
}
__device__ __forceinline__ void mma16816(float* c, const uint32_t* a, uint32_t b0, uint32_t b1) {
    asm volatile("mma.sync.aligned.m16n8k16.row.col.f32.bf16.bf16.f32 "
        "{%0,%1,%2,%3},{%4,%5,%6,%7},{%8,%9},{%0,%1,%2,%3};"
        : "+f"(c[0]), "+f"(c[1]), "+f"(c[2]), "+f"(c[3])
        : "r"(a[0]), "r"(a[1]), "r"(a[2]), "r"(a[3]), "r"(b0), "r"(b1));
}

__device__ __forceinline__ void store_hilo(__nv_bfloat16* hi, __nv_bfloat16* lo,
                                           size_t off, float v0, float v1) {
    __nv_bfloat16 h0 = __float2bfloat16(v0);
    __nv_bfloat16 h1 = __float2bfloat16(v1);
    __nv_bfloat16 l0 = __float2bfloat16(v0 - __bfloat162float(h0));
    __nv_bfloat16 l1 = __float2bfloat16(v1 - __bfloat162float(h1));
    __nv_bfloat162 hp; hp.x = h0; hp.y = h1;
    __nv_bfloat162 lp; lp.x = l0; lp.y = l1;
    *(__nv_bfloat162*)(hi + off) = hp;
    *(__nv_bfloat162*)(lo + off) = lp;
}

union BF4 { uint2 u; __nv_bfloat162 p[2]; };

__device__ __forceinline__ void split4(const float* v, BF4& hv, BF4& lv) {
    __nv_bfloat16 h0 = __float2bfloat16(v[0]);
    __nv_bfloat16 h1 = __float2bfloat16(v[1]);
    __nv_bfloat16 h2 = __float2bfloat16(v[2]);
    __nv_bfloat16 h3 = __float2bfloat16(v[3]);
    hv.p[0].x = h0; hv.p[0].y = h1; hv.p[1].x = h2; hv.p[1].y = h3;
    lv.p[0].x = __float2bfloat16(v[0] - __bfloat162float(h0));
    lv.p[0].y = __float2bfloat16(v[1] - __bfloat162float(h1));
    lv.p[1].x = __float2bfloat16(v[2] - __bfloat162float(h2));
    lv.p[1].y = __float2bfloat16(v[3] - __bfloat162float(h3));
}

// ---------------- kernel: extract diagonal blocks -> bf16 hi/lo (4 elems/thread) ----------------
__global__ void extract_kernel(const float* __restrict__ x) {
    int q = blockIdx.x * blockDim.x + threadIdx.x;        // quad index
    if (q >= ROWS * KPAD1 / 4) return;
    int f0 = (q % (KPAD1 / 4)) * 4;
    int sb = q / (KPAD1 / 4);
    int b  = sb & (BATCH - 1);
    int s  = sb >> 8;
    const float* xb = x + (size_t)b * (TOTAL_R * TOTAL_R);
    float v[4];
    #pragma unroll
    for (int e = 0; e < 4; e++) {
        int f = f0 + e;
        float vv = 0.f;
        if (f < FLAT) {
            int i = f / REGIONS;
            int j = f - i * REGIONS;
            vv = xb[(s * REGIONS + i) * TOTAL_R + (s * REGIONS + j)];
        }
        v[e] = vv;
    }
    BF4 hv, lv; split4(v, hv, lv);
    size_t off = (size_t)sb * KPAD1 + f0;
    *(uint2*)(g_flat_hi + off) = hv.u;
    *(uint2*)(g_flat_lo + off) = lv.u;
}

// ---------------- W1 transpose+split: [s][2500][512] -> [s][512][2560] ----------------
__global__ void wconv_w1_kernel(const float* __restrict__ src) {
    __shared__ float tile[32][33];
    int k0 = blockIdx.x * 32, n0 = blockIdx.y * 32, z = blockIdx.z;
    const float* sp = src + (size_t)z * FLAT * HIDDEN;
    size_t dbase = (size_t)z * HIDDEN * KPAD1;
    int tid = threadIdx.x;
    int tx = tid & 31, ty = tid >> 5;       // 256 threads
    #pragma unroll
    for (int r = 0; r < 4; r++) {
        int k = k0 + ty + r * 8;
        tile[ty + r * 8][tx] = (k < FLAT) ? sp[(size_t)k * HIDDEN + n0 + tx] : 0.f;
    }
    __syncthreads();
    int n = tid >> 3, kq = (tid & 7) * 4;
    float v[4];
    #pragma unroll
    for (int i = 0; i < 4; i++) v[i] = tile[kq + i][n];
    BF4 hv, lv; split4(v, hv, lv);
    size_t off = dbase + (size_t)(n0 + n) * KPAD1 + k0 + kq;
    *(uint2*)(g_W1T_hi + off) = hv.u;
    *(uint2*)(g_W1T_lo + off) = lv.u;
}

// ---------------- batched 512x512 transpose+split (13 slices, one launch) ----------------
struct W13 {
    const float* src[13];
    __nv_bfloat16* dhi[13];
    __nv_bfloat16* dlo[13];
};
__global__ void wconv512_kernel(W13 a) {
    __shared__ float tile[32][33];
    int z = blockIdx.z;
    const float* sp = a.src[z];
    __nv_bfloat16* dhi = a.dhi[z];
    __nv_bfloat16* dlo = a.dlo[z];
    int k0 = blockIdx.x * 32, n0 = blockIdx.y * 32;
    int tid = threadIdx.x;
    int tx = tid & 31, ty = tid >> 5;
    #pragma unroll
    for (int r = 0; r < 4; r++) {
        int k = k0 + ty + r * 8;
        tile[ty + r * 8][tx] = sp[(size_t)k * HIDDEN + n0 + tx];
    }
    __syncthreads();
    int n = tid >> 3, kq = (tid & 7) * 4;
    float v[4];
    #pragma unroll
    for (int i = 0; i < 4; i++) v[i] = tile[kq + i][n];
    BF4 hv, lv; split4(v, hv, lv);
    size_t off = (size_t)(n0 + n) * HIDDEN + k0 + kq;
    *(uint2*)(dhi + off) = hv.u;
    *(uint2*)(dlo + off) = lv.u;
}

// ---------------- mma.sync GEMM: C[2048][N] = A[2048][K] * W^T + epilogue ----------------
// C = Ah*Bh + Ah*Bl + Al*Bh, fp32 accum. BM=BN=64, BK=64, 3-stage cp.async pipeline,
// 8 warps as 2(m) x 4(n), warp tile 32x16. 2 CTAs/SM.
// EP: 0 relu->hi/lo | 1 f32 | 2 qkv split f32 | 3 hi/lo | 4 resid+permute f32
template<int EP>
__global__ __launch_bounds__(256, 2) void tc_gemm(
    const __nv_bfloat16* __restrict__ Ahi, const __nv_bfloat16* __restrict__ Alo, int sA,
    const __nv_bfloat16* __restrict__ Bhi, const __nv_bfloat16* __restrict__ Blo, int sB,
    long bSub, int Ksteps,
    const float* __restrict__ bias,
    float* __restrict__ o32,
    __nv_bfloat16* __restrict__ oHi, __nv_bfloat16* __restrict__ oLo,
    const float* __restrict__ resid,
    float* __restrict__ oq, float* __restrict__ okk, float* __restrict__ ov,
    const float* __restrict__ bq, const float* __restrict__ bk, const float* __restrict__ bv)
{
    extern __shared__ __align__(128) char smem[];
    const uint32_t sbase = smem_u32(smem);
    const int tid = threadIdx.x;
    const int mBase = blockIdx.y * BM;
    const int nBase = blockIdx.x * BN;
    const int sIdx = blockIdx.y >> 2;        // 4 M-tiles (256 rows) per subnet

    const __nv_bfloat16* aH = Ahi + (size_t)mBase * sA;
    const __nv_bfloat16* aL = Alo + (size_t)mBase * sA;
    size_t boff = (bSub > 0 ? (size_t)sIdx * (size_t)bSub : 0) + (size_t)nBase * sB;
    const __nv_bfloat16* bH = Bhi + boff;
    const __nv_bfloat16* bL = Blo + boff;
    const float* biasP = bias ? (bias + (bSub > 0 ? sIdx * HIDDEN : 0)) : bias;

    // ---- async-copy one K-chunk; ALWAYS commits exactly one group ----
    auto issue = [&](int chunk) {
        if (chunk < Ksteps) {
            const uint32_t st = sbase + (chunk % NSTAGE) * STAGE;
            const int k0 = chunk * BK;
            // A: 64 rows x 8 16B-chunks = 512; 2 per thread, x2 arrays
            #pragma unroll
            for (int i = 0; i < 2; i++) {
                int idx = tid + i * 256;
                int row = idx >> 3, c = idx & 7;
                uint32_t so = st + row * ASTRIDE + c * 16;
                cpa16(so,           aH + (size_t)row * sA + k0 + c * 8);
                cpa16(so + T_BYTES, aL + (size_t)row * sA + k0 + c * 8);
            }
            // B: same shape
            #pragma unroll
            for (int i = 0; i < 2; i++) {
                int idx = tid + i * 256;
                int row = idx >> 3, c = idx & 7;
                uint32_t so = st + 2 * T_BYTES + row * ASTRIDE + c * 16;
                cpa16(so,           bH + (size_t)row * sB + k0 + c * 8);
                cpa16(so + T_BYTES, bL + (size_t)row * sB + k0 + c * 8);
            }
        }
        cpa_commit();
    };

    issue(0); issue(1);

    const int wid = tid >> 5, lane = tid & 31;
    const int wm = wid >> 2, wn = wid & 3;            // 2 x 4 warps, warp tile 32x16
    const uint32_t lrow = lane & 15;
    const uint32_t lcol = (lane >> 4) * 16;

    float acc[2][2][4];
    #pragma unroll
    for (int i = 0; i < 2; i++)
        #pragma unroll
        for (int j = 0; j < 2; j++)
            #pragma unroll
            for (int t = 0; t < 4; t++) acc[i][j][t] = 0.f;

    for (int s = 0; s < Ksteps; ++s) {
        cpa_wait<1>();                 // stage s landed
        __syncthreads();               // all warps done with buffer (s-1)%3
        issue(s + 2);                  // refill freed buffer, overlaps compute
        const uint32_t st = sbase + (s % NSTAGE) * STAGE;
        #pragma unroll
        for (int kk = 0; kk < 4; ++kk) {
            uint32_t aHf[2][4], aLf[2][4], bHf[4], bLf[4];
            #pragma unroll
            for (int am = 0; am < 2; am++) {
                uint32_t ad = st + (wm * 32 + am * 16 + lrow) * ASTRIDE + kk * 32 + lcol;
                ldm4(ad,           aHf[am]);
                ldm4(ad + T_BYTES, aLf[am]);
            }
            {
                uint32_t bd = st + 2 * T_BYTES + (wn * 16 + lrow) * ASTRIDE + kk * 32 + lcol;
                ldm4(bd,           bHf);
                ldm4(bd + T_BYTES, bLf);
            }
            #pragma unroll
            for (int am = 0; am < 2; am++) {
                mma16816(acc[am][0], aHf[am], bHf[0], bHf[2]);
                mma16816(acc[am][1], aHf[am], bHf[1], bHf[3]);
                mma16816(acc[am][0], aHf[am], bLf[0], bLf[2]);
                mma16816(acc[am][1], aHf[am], bLf[1], bLf[3]);
                mma16816(acc[am][0], aLf[am], bHf[0], bHf[2]);
                mma16816(acc[am][1], aLf[am], bHf[1], bHf[3]);
            }
        }
    }

    // ---- epilogue: registers -> global ----
    #pragma unroll
    for (int am = 0; am < 2; am++) {
        #pragma unroll
        for (int an = 0; an < 2; an++) {
            int m0 = mBase + wm * 32 + am * 16 + (lane >> 2);
            int g  = nBase + wn * 16 + an * 8 + (lane & 3) * 2;
            #pragma unroll
            for (int half = 0; half < 2; half++) {
                int m = m0 + half * 8;
                float v0 = acc[am][an][half * 2];
                float v1 = acc[am][an][half * 2 + 1];
                if (EP == 0) {                          // relu -> h hi/lo
                    v0 = fmaxf(v0 + biasP[g], 0.f);
                    v1 = fmaxf(v1 + biasP[g + 1], 0.f);
                    store_hilo(oHi, oLo, (size_t)m * HIDDEN + g, v0, v1);
                } else if (EP == 1) {                   // xsub fp32
                    v0 += biasP[g]; v1 += biasP[g + 1];
                    *(float2*)(o32 + (size_t)m * HIDDEN + g) = make_float2(v0, v1);
                } else if (EP == 2) {                   // qkv fp32 split
                    int which = g >> 9, lc = g & 511;
                    const float* bb = (which == 0) ? bq : (which == 1) ? bk : bv;
                    float* dst = (which == 0) ? oq : (which == 1) ? okk : ov;
                    v0 += bb[lc]; v1 += bb[lc + 1];
                    *(float2*)(dst + (size_t)m * HIDDEN + lc) = make_float2(v0, v1);
                } else if (EP == 3) {                   // t hi/lo
                    v0 += biasP[g]; v1 += biasP[g + 1];
                    store_hilo(oHi, oLo, (size_t)m * HIDDEN + g, v0, v1);
                } else {                                // out = . + bp + xsub, (b,s) order
                    v0 += biasP[g] + resid[(size_t)m * HIDDEN + g];
                    v1 += biasP[g + 1] + resid[(size_t)m * HIDDEN + g + 1];
                    int bb2 = m & (BATCH - 1), ss = m >> 8;
                    *(float2*)(o32 + ((size_t)((bb2 << 3) + ss)) * HIDDEN + g) = make_float2(v0, v1);
                }
            }
        }
    }
}

// ---------------- LayerNorm: xsub fp32 -> xn hi/lo ----------------
__global__ __launch_bounds__(256) void ln_kernel(const float* __restrict__ lng,
                                                 const float* __restrict__ lnb)
{
    int r = blockIdx.x, t = threadIdx.x;
    const float* xs = g_xsub + (size_t)r * HIDDEN;
    float v0 = xs[t], v1 = xs[t + 256];
    float s = v0 + v1, q = v0 * v0 + v1 * v1;
    #pragma unroll
    for (int o = 16; o > 0; o >>= 1) {
        s += __shfl_xor_sync(0xFFFFFFFFu, s, o);
        q += __shfl_xor_sync(0xFFFFFFFFu, q, o);
    }
    __shared__ float ss[8], sq[8];
    int w = t >> 5, l = t & 31;
    if (l == 0) { ss[w] = s; sq[w] = q; }
    __syncthreads();
    if (w == 0) {
        float a = (l < 8) ? ss[l] : 0.f;
        float c = (l < 8) ? sq[l] : 0.f;
        #pragma unroll
        for (int o = 4; o > 0; o >>= 1) {
            a += __shfl_xor_sync(0xFFFFFFFFu, a, o);
            c += __shfl_xor_sync(0xFFFFFFFFu, c, o);
        }
        if (l == 0) { ss[0] = a; sq[0] = c; }
    }
    __syncthreads();
    float mean = ss[0] * (1.f / HIDDEN);
    float var  = sq[0] * (1.f / HIDDEN) - mean * mean;
    float inv  = rsqrtf(var + LN_EPS);
    float o0 = (v0 - mean) * inv * lng[t] + lnb[t];
    float o1 = (v1 - mean) * inv * lng[t + 256] + lnb[t + 256];
    size_t base = (size_t)r * HIDDEN;
    __nv_bfloat16 h0 = __float2bfloat16(o0);
    __nv_bfloat16 h1 = __float2bfloat16(o1);
    g_xn_hi[base + t] = h0;
    g_xn_lo[base + t] = __float2bfloat16(o0 - __bfloat162float(h0));
    g_xn_hi[base + t + 256] = h1;
    g_xn_lo[base + t + 256] = __float2bfloat16(o1 - __bfloat162float(h1));
}

// ---------------- attention: q,k,v fp32 -> ctx hi/lo ----------------
__global__ __launch_bounds__(256) void attn_kernel()
{
    __shared__ float q_s[NUM_SUBNETS][520];
    __shared__ float k_s[NUM_SUBNETS][520];
    __shared__ float sc[HEADS][NUM_SUBNETS][NUM_SUBNETS];

    int b = blockIdx.x;
    int tid = threadIdx.x;

    for (int i = tid; i < NUM_SUBNETS * HIDDEN; i += 256) {
        int m = i >> 9, c = i & 511;
        size_t gi = ((size_t)(m * BATCH + b)) * HIDDEN + c;
        q_s[m][c] = g_q[gi];
        k_s[m][c] = g_k[gi];
    }
    __syncthreads();

    int h = tid >> 5, l = tid & 31;

    #pragma unroll
    for (int pp = 0; pp < 2; pp++) {
        int p = l + pp * 32;
        int m = p >> 3, n = p & 7;
        const float* qp = &q_s[m][h * HEAD_DIM];
        const float* kp = &k_s[n][h * HEAD_DIM];
        float sv = 0.f;
        #pragma unroll
        for (int d = 0; d < HEAD_DIM; d++) sv += qp[d] * kp[d];
        sv *= 0.125f;
        sc[h][m][n] = (m == n) ? 0.f : sv;
    }
    __syncwarp();

    if (l < NUM_SUBNETS) {
        float mx = -1e30f;
        #pragma unroll
        for (int n = 0; n < 8; n++) mx = fmaxf(mx, sc[h][l][n]);
        float e[8], sum = 0.f;
        #pragma unroll
        for (int n = 0; n < 8; n++) { e[n] = expf(sc[h][l][n] - mx); sum += e[n]; }
        float inv = 1.f / sum;
        #pragma unroll
        for (int n = 0; n < 8; n++) sc[h][l][n] = e[n] * inv;
    }
    __syncwarp();

    #pragma unroll
    for (int dd = 0; dd < 2; dd++) {
        int d = l + dd * 32;
        float vv[8];
        #pragma unroll
        for (int n = 0; n < 8; n++)
            vv[n] = g_v[((size_t)(n * BATCH + b)) * HIDDEN + h * HEAD_DIM + d];
        #pragma unroll
        for (int m = 0; m < 8; m++) {
            float cv = 0.f;
            #pragma unroll
            for (int n = 0; n < 8; n++) cv += sc[h][m][n] * vv[n];
            size_t off = ((size_t)(m * BATCH + b)) * HIDDEN + h * HEAD_DIM + d;
            __nv_bfloat16 hi = __float2bfloat16(cv);
            g_ctx_hi[off] = hi;
            g_ctx_lo[off] = __float2bfloat16(cv - __bfloat162float(hi));
        }
    }
}

// ---------------- launch ----------------
extern "C" void kernel_launch(void* const* d_in, const int* in_sizes, int n_in,
                              void* d_out, int out_size)
{
    (void)in_sizes; (void)n_in; (void)out_size;
    const float* x    = (const float*)d_in[0];
    const float* W1   = (const float*)d_in[2];
    const float* b1   = (const float*)d_in[3];
    const float* W2   = (const float*)d_in[4];
    const float* b2   = (const float*)d_in[5];
    const float* ln_g = (const float*)d_in[6];
    const float* ln_b = (const float*)d_in[7];
    const float* Wq   = (const float*)d_in[8];
    const float* bq   = (const float*)d_in[9];
    const float* Wk   = (const float*)d_in[10];
    const float* bk   = (const float*)d_in[11];
    const float* Wv   = (const float*)d_in[12];
    const float* bv   = (const float*)d_in[13];
    const float* Wo   = (const float*)d_in[14];
    const float* bo   = (const float*)d_in[15];
    const float* Wp   = (const float*)d_in[16];
    const float* bp   = (const float*)d_in[17];
    float* out = (float*)d_out;

    __nv_bfloat16 *flat_hi, *flat_lo, *W1T_hi, *W1T_lo, *W2T_hi, *W2T_lo;
    __nv_bfloat16 *WqkvT_hi, *WqkvT_lo, *WoT_hi, *WoT_lo, *WpT_hi, *WpT_lo;
    __nv_bfloat16 *h_hi, *h_lo, *xn_hi, *xn_lo, *ctx_hi, *ctx_lo, *t_hi, *t_lo;
    float *xsub, *pq, *pk, *pv;
    cudaGetSymbolAddress((void**)&flat_hi, g_flat_hi);
    cudaGetSymbolAddress((void**)&flat_lo, g_flat_lo);
    cudaGetSymbolAddress((void**)&W1T_hi,  g_W1T_hi);
    cudaGetSymbolAddress((void**)&W1T_lo,  g_W1T_lo);
    cudaGetSymbolAddress((void**)&W2T_hi,  g_W2T_hi);
    cudaGetSymbolAddress((void**)&W2T_lo,  g_W2T_lo);
    cudaGetSymbolAddress((void**)&WqkvT_hi, g_WqkvT_hi);
    cudaGetSymbolAddress((void**)&WqkvT_lo, g_WqkvT_lo);
    cudaGetSymbolAddress((void**)&WoT_hi,  g_WoT_hi);
    cudaGetSymbolAddress((void**)&WoT_lo,  g_WoT_lo);
    cudaGetSymbolAddress((void**)&WpT_hi,  g_WpT_hi);
    cudaGetSymbolAddress((void**)&WpT_lo,  g_WpT_lo);
    cudaGetSymbolAddress((void**)&h_hi,    g_h_hi);
    cudaGetSymbolAddress((void**)&h_lo,    g_h_lo);
    cudaGetSymbolAddress((void**)&xn_hi,   g_xn_hi);
    cudaGetSymbolAddress((void**)&xn_lo,   g_xn_lo);
    cudaGetSymbolAddress((void**)&ctx_hi,  g_ctx_hi);
    cudaGetSymbolAddress((void**)&ctx_lo,  g_ctx_lo);
    cudaGetSymbolAddress((void**)&t_hi,    g_t_hi);
    cudaGetSymbolAddress((void**)&t_lo,    g_t_lo);
    cudaGetSymbolAddress((void**)&xsub,    g_xsub);
    cudaGetSymbolAddress((void**)&pq,      g_q);
    cudaGetSymbolAddress((void**)&pk,      g_k);
    cudaGetSymbolAddress((void**)&pv,      g_v);

    cudaFuncSetAttribute(tc_gemm<0>, cudaFuncAttributeMaxDynamicSharedMemorySize, GEMM_SMEM);
    cudaFuncSetAttribute(tc_gemm<1>, cudaFuncAttributeMaxDynamicSharedMemorySize, GEMM_SMEM);
    cudaFuncSetAttribute(tc_gemm<2>, cudaFuncAttributeMaxDynamicSharedMemorySize, GEMM_SMEM);
    cudaFuncSetAttribute(tc_gemm<3>, cudaFuncAttributeMaxDynamicSharedMemorySize, GEMM_SMEM);
    cudaFuncSetAttribute(tc_gemm<4>, cudaFuncAttributeMaxDynamicSharedMemorySize, GEMM_SMEM);

    // ---- input conversions ----
    extract_kernel<<<(ROWS * KPAD1 / 4 + 255) / 256, 256>>>(x);
    wconv_w1_kernel<<<dim3(KPAD1 / 32, HIDDEN / 32, NUM_SUBNETS), 256>>>(W1);

    W13 wa;
    for (int z = 0; z < 8; z++) {
        wa.src[z] = W2 + (size_t)z * HIDDEN * HIDDEN;
        wa.dhi[z] = W2T_hi + (size_t)z * HIDDEN * HIDDEN;
        wa.dlo[z] = W2T_lo + (size_t)z * HIDDEN * HIDDEN;
    }
    const float* srcs[5] = { Wq, Wk, Wv, Wo, Wp };
    __nv_bfloat16* dhis[5] = { WqkvT_hi, WqkvT_hi + 512 * 512, WqkvT_hi + 1024 * 512, WoT_hi, WpT_hi };
    __nv_bfloat16* dlos[5] = { WqkvT_lo, WqkvT_lo + 512 * 512, WqkvT_lo + 1024 * 512, WoT_lo, WpT_lo };
    for (int z = 0; z < 5; z++) {
        wa.src[8 + z] = srcs[z];
        wa.dhi[8 + z] = dhis[z];
        wa.dlo[8 + z] = dlos[z];
    }
    wconv512_kernel<<<dim3(16, 16, 13), 256>>>(wa);

    dim3 g512(HIDDEN / BN, ROWS / BM);        // 8 x 32 = 256 CTAs
    dim3 gqkv(3 * HIDDEN / BN, ROWS / BM);    // 24 x 32 = 768 CTAs

    // GEMM1: h = relu(flat @ W1 + b1)
    tc_gemm<0><<<g512, 256, GEMM_SMEM>>>(flat_hi, flat_lo, KPAD1, W1T_hi, W1T_lo, KPAD1,
        (long)HIDDEN * KPAD1, KPAD1 / BK, b1, nullptr, h_hi, h_lo,
        nullptr, nullptr, nullptr, nullptr, nullptr, nullptr, nullptr);
    // GEMM2: xsub = h @ W2 + b2
    tc_gemm<1><<<g512, 256, GEMM_SMEM>>>(h_hi, h_lo, HIDDEN, W2T_hi, W2T_lo, HIDDEN,
        (long)HIDDEN * HIDDEN, HIDDEN / BK, b2, xsub, nullptr, nullptr,
        nullptr, nullptr, nullptr, nullptr, nullptr, nullptr, nullptr);
    // LN -> xn hi/lo
    ln_kernel<<<ROWS, 256>>>(ln_g, ln_b);
    // QKV fused
    tc_gemm<2><<<gqkv, 256, GEMM_SMEM>>>(xn_hi, xn_lo, HIDDEN, WqkvT_hi, WqkvT_lo, HIDDEN,
        0L, HIDDEN / BK, nullptr, nullptr, nullptr, nullptr,
        nullptr, pq, pk, pv, bq, bk, bv);
    // attention -> ctx hi/lo
    attn_kernel<<<BATCH, 256>>>();
    // O: t = ctx @ Wo + bo
    tc_gemm<3><<<g512, 256, GEMM_SMEM>>>(ctx_hi, ctx_lo, HIDDEN, WoT_hi, WoT_lo, HIDDEN,
        0L, HIDDEN / BK, bo, nullptr, t_hi, t_lo,
        nullptr, nullptr, nullptr, nullptr, nullptr, nullptr, nullptr);
    // P: out = t @ Wp + bp + xsub (permuted to (b,s))
    tc_gemm<4><<<g512, 256, GEMM_SMEM>>>(t_hi, t_lo, HIDDEN, WpT_hi, WpT_lo, HIDDEN,
        0L, HIDDEN / BK, bp, out, nullptr, nullptr,
        xsub, nullptr, nullptr, nullptr, nullptr, nullptr, nullptr);
}

// round 6
// speedup vs baseline: 3.3751x; 1.0092x over previous
#include <cuda_runtime.h>
#include <cuda_bf16.h>
#include <math.h>
#include <cstdint>

// ---------------- problem constants ----------------
#define NUM_SUBNETS 8
#define REGIONS     50
#define TOTAL_R     400
#define HIDDEN      512
#define HEADS       8
#define HEAD_DIM    64
#define BATCH       256
#define FLAT        2500
#define ROWS        (NUM_SUBNETS * BATCH)   // 2048
#define LN_EPS      1e-5f
#define KPAD1       2560                    // FLAT padded to multiple of 64

// GEMM tiling
#define BM 64
#define BN 64
#define BK 64
#define ASTRIDE 144                         // bytes per 64-col bf16 row (128 + 16 pad)
#define T_BYTES (BM * ASTRIDE)              // 9216 per tile array
#define STAGE   (4 * T_BYTES)               // 36864 (Ahi,Alo,Bhi,Blo)
#define NSTAGE  3
#define GEMM_SMEM (NSTAGE * STAGE)          // 110592 -> 2 CTAs/SM

typedef unsigned long long u64;

// ---------------- scratch (device globals) ----------------
__device__ __nv_bfloat16 g_flat_hi[ROWS * KPAD1];
__device__ __nv_bfloat16 g_flat_lo[ROWS * KPAD1];
__device__ __nv_bfloat16 g_W1T_hi[NUM_SUBNETS * HIDDEN * KPAD1];
__device__ __nv_bfloat16 g_W1T_lo[NUM_SUBNETS * HIDDEN * KPAD1];
__device__ __nv_bfloat16 g_W2T_hi[NUM_SUBNETS * HIDDEN * HIDDEN];
__device__ __nv_bfloat16 g_W2T_lo[NUM_SUBNETS * HIDDEN * HIDDEN];
__device__ __nv_bfloat16 g_WqkvT_hi[3 * HIDDEN * HIDDEN];
__device__ __nv_bfloat16 g_WqkvT_lo[3 * HIDDEN * HIDDEN];
__device__ __nv_bfloat16 g_WoT_hi[HIDDEN * HIDDEN];
__device__ __nv_bfloat16 g_WoT_lo[HIDDEN * HIDDEN];
__device__ __nv_bfloat16 g_WpT_hi[HIDDEN * HIDDEN];
__device__ __nv_bfloat16 g_WpT_lo[HIDDEN * HIDDEN];

__device__ __nv_bfloat16 g_h_hi[ROWS * HIDDEN];
__device__ __nv_bfloat16 g_h_lo[ROWS * HIDDEN];
__device__ float         g_xsub[ROWS * HIDDEN];
__device__ __nv_bfloat16 g_xn_hi[ROWS * HIDDEN];
__device__ __nv_bfloat16 g_xn_lo[ROWS * HIDDEN];
__device__ float         g_q[ROWS * HIDDEN];
__device__ float         g_k[ROWS * HIDDEN];
__device__ float         g_v[ROWS * HIDDEN];
__device__ __nv_bfloat16 g_ctx_hi[ROWS * HIDDEN];
__device__ __nv_bfloat16 g_ctx_lo[ROWS * HIDDEN];
__device__ __nv_bfloat16 g_t_hi[ROWS * HIDDEN];
__device__ __nv_bfloat16 g_t_lo[ROWS * HIDDEN];

// ---------------- PTX helpers (sm_80-ratified only) ----------------
__device__ __forceinline__ uint32_t smem_u32(const void* p) {
    uint32_t a;
    asm("{ .reg .u64 t; cvta.to.shared.u64 t, %1; cvt.u32.u64 %0, t; }" : "=r"(a) : "l"(p));
    return a;
}
__device__ __forceinline__ void cpa16(uint32_t s, const void* g) {
    asm volatile("cp.async.cg.shared.global [%0], [%1], 16;" :: "r"(s), "l"(g));
}
__device__ __forceinline__ void cpa_commit() {
    asm volatile("cp.async.commit_group;" ::: "memory");
}
template<int N> __device__ __forceinline__ void cpa_wait() {
    asm volatile("cp.async.wait_group %0;" :: "n"(N) : "memory");
}
__device__ __forceinline__ void ldm4(uint32_t a, uint32_t* r) {
    asm volatile("ldmatrix.sync.aligned.m8n8.x4.shared.b16 {%0,%1,%2,%3}, [%4];"
        : "=r"(r[0]), "=r"(r[1]), "=r"(r[2]), "=r"(r[3]) : "r"(a));
}
__device__ __forceinline__ void mma16816(float* c, const uint32_t* a, uint32_t b0, uint32_t b1) {
    asm volatile("mma.sync.aligned.m16n8k16.row.col.f32.bf16.bf16.f32 "
        "{%0,%1,%2,%3},{%4,%5,%6,%7},{%8,%9},{%0,%1,%2,%3};"
        : "+f"(c[0]), "+f"(c[1]), "+f"(c[2]), "+f"(c[3])
        : "r"(a[0]), "r"(a[1]), "r"(a[2]), "r"(a[3]), "r"(b0), "r"(b1));
}

__device__ __forceinline__ void store_hilo(__nv_bfloat16* hi, __nv_bfloat16* lo,
                                           size_t off, float v0, float v1) {
    __nv_bfloat16 h0 = __float2bfloat16(v0);
    __nv_bfloat16 h1 = __float2bfloat16(v1);
    __nv_bfloat16 l0 = __float2bfloat16(v0 - __bfloat162float(h0));
    __nv_bfloat16 l1 = __float2bfloat16(v1 - __bfloat162float(h1));
    __nv_bfloat162 hp; hp.x = h0; hp.y = h1;
    __nv_bfloat162 lp; lp.x = l0; lp.y = l1;
    *(__nv_bfloat162*)(hi + off) = hp;
    *(__nv_bfloat162*)(lo + off) = lp;
}

union BF4 { uint2 u; __nv_bfloat162 p[2]; };

__device__ __forceinline__ void split4(const float* v, BF4& hv, BF4& lv) {
    __nv_bfloat16 h0 = __float2bfloat16(v[0]);
    __nv_bfloat16 h1 = __float2bfloat16(v[1]);
    __nv_bfloat16 h2 = __float2bfloat16(v[2]);
    __nv_bfloat16 h3 = __float2bfloat16(v[3]);
    hv.p[0].x = h0; hv.p[0].y = h1; hv.p[1].x = h2; hv.p[1].y = h3;
    lv.p[0].x = __float2bfloat16(v[0] - __bfloat162float(h0));
    lv.p[0].y = __float2bfloat16(v[1] - __bfloat162float(h1));
    lv.p[1].x = __float2bfloat16(v[2] - __bfloat162float(h2));
    lv.p[1].y = __float2bfloat16(v[3] - __bfloat162float(h3));
}

// ---------------- kernel: extract diagonal blocks -> bf16 hi/lo (4 elems/thread) ----------------
__global__ void extract_kernel(const float* __restrict__ x) {
    int q = blockIdx.x * blockDim.x + threadIdx.x;        // quad index
    if (q >= ROWS * KPAD1 / 4) return;
    int f0 = (q % (KPAD1 / 4)) * 4;
    int sb = q / (KPAD1 / 4);
    int b  = sb & (BATCH - 1);
    int s  = sb >> 8;
    const float* xb = x + (size_t)b * (TOTAL_R * TOTAL_R);
    float v[4];
    #pragma unroll
    for (int e = 0; e < 4; e++) {
        int f = f0 + e;
        float vv = 0.f;
        if (f < FLAT) {
            int i = f / REGIONS;
            int j = f - i * REGIONS;
            vv = xb[(s * REGIONS + i) * TOTAL_R + (s * REGIONS + j)];
        }
        v[e] = vv;
    }
    BF4 hv, lv; split4(v, hv, lv);
    size_t off = (size_t)sb * KPAD1 + f0;
    *(uint2*)(g_flat_hi + off) = hv.u;
    *(uint2*)(g_flat_lo + off) = lv.u;
}

// ---------------- W1 transpose+split: [s][2500][512] -> [s][512][2560] ----------------
__global__ void wconv_w1_kernel(const float* __restrict__ src) {
    __shared__ float tile[32][33];
    int k0 = blockIdx.x * 32, n0 = blockIdx.y * 32, z = blockIdx.z;
    const float* sp = src + (size_t)z * FLAT * HIDDEN;
    size_t dbase = (size_t)z * HIDDEN * KPAD1;
    int tid = threadIdx.x;
    int tx = tid & 31, ty = tid >> 5;       // 256 threads
    #pragma unroll
    for (int r = 0; r < 4; r++) {
        int k = k0 + ty + r * 8;
        tile[ty + r * 8][tx] = (k < FLAT) ? sp[(size_t)k * HIDDEN + n0 + tx] : 0.f;
    }
    __syncthreads();
    int n = tid >> 3, kq = (tid & 7) * 4;
    float v[4];
    #pragma unroll
    for (int i = 0; i < 4; i++) v[i] = tile[kq + i][n];
    BF4 hv, lv; split4(v, hv, lv);
    size_t off = dbase + (size_t)(n0 + n) * KPAD1 + k0 + kq;
    *(uint2*)(g_W1T_hi + off) = hv.u;
    *(uint2*)(g_W1T_lo + off) = lv.u;
}

// ---------------- batched 512x512 transpose+split (13 slices, one launch) ----------------
struct W13 {
    const float* src[13];
    __nv_bfloat16* dhi[13];
    __nv_bfloat16* dlo[13];
};
__global__ void wconv512_kernel(W13 a) {
    __shared__ float tile[32][33];
    int z = blockIdx.z;
    const float* sp = a.src[z];
    __nv_bfloat16* dhi = a.dhi[z];
    __nv_bfloat16* dlo = a.dlo[z];
    int k0 = blockIdx.x * 32, n0 = blockIdx.y * 32;
    int tid = threadIdx.x;
    int tx = tid & 31, ty = tid >> 5;
    #pragma unroll
    for (int r = 0; r < 4; r++) {
        int k = k0 + ty + r * 8;
        tile[ty + r * 8][tx] = sp[(size_t)k * HIDDEN + n0 + tx];
    }
    __syncthreads();
    int n = tid >> 3, kq = (tid & 7) * 4;
    float v[4];
    #pragma unroll
    for (int i = 0; i < 4; i++) v[i] = tile[kq + i][n];
    BF4 hv, lv; split4(v, hv, lv);
    size_t off = (size_t)(n0 + n) * HIDDEN + k0 + kq;
    *(uint2*)(dhi + off) = hv.u;
    *(uint2*)(dlo + off) = lv.u;
}

// ---------------- mma.sync GEMM: C[2048][N] = A[2048][K] * W^T + epilogue ----------------
// C = Ah*Bh + Ah*Bl + Al*Bh, fp32 accum. BM=BN=64, BK=64.
// 8 warps as (wm 2) x (wn 2) x (wk 2): warp tile 32x32, K split across wk;
// k-halves reduced through SMEM at the end. 3 MMAs per ldmatrix.
// EP: 0 relu->hi/lo | 1 f32 | 2 qkv split f32 | 3 hi/lo | 4 resid+permute f32
template<int EP>
__global__ __launch_bounds__(256, 2) void tc_gemm(
    const __nv_bfloat16* __restrict__ Ahi, const __nv_bfloat16* __restrict__ Alo, int sA,
    const __nv_bfloat16* __restrict__ Bhi, const __nv_bfloat16* __restrict__ Blo, int sB,
    long bSub, int Ksteps,
    const float* __restrict__ bias,
    float* __restrict__ o32,
    __nv_bfloat16* __restrict__ oHi, __nv_bfloat16* __restrict__ oLo,
    const float* __restrict__ resid,
    float* __restrict__ oq, float* __restrict__ okk, float* __restrict__ ov,
    const float* __restrict__ bq, const float* __restrict__ bk, const float* __restrict__ bv)
{
    extern __shared__ __align__(128) char smem[];
    const uint32_t sbase = smem_u32(smem);
    const int tid = threadIdx.x;
    const int mBase = blockIdx.y * BM;
    const int nBase = blockIdx.x * BN;
    const int sIdx = blockIdx.y >> 2;        // 4 M-tiles (256 rows) per subnet

    const __nv_bfloat16* aH = Ahi + (size_t)mBase * sA;
    const __nv_bfloat16* aL = Alo + (size_t)mBase * sA;
    size_t boff = (bSub > 0 ? (size_t)sIdx * (size_t)bSub : 0) + (size_t)nBase * sB;
    const __nv_bfloat16* bH = Bhi + boff;
    const __nv_bfloat16* bL = Blo + boff;
    const float* biasP = bias ? (bias + (bSub > 0 ? sIdx * HIDDEN : 0)) : bias;

    // ---- async-copy one K-chunk; ALWAYS commits exactly one group ----
    auto issue = [&](int chunk) {
        if (chunk < Ksteps) {
            const uint32_t st = sbase + (chunk % NSTAGE) * STAGE;
            const int k0 = chunk * BK;
            #pragma unroll
            for (int i = 0; i < 2; i++) {
                int idx = tid + i * 256;
                int row = idx >> 3, c = idx & 7;
                uint32_t so = st + row * ASTRIDE + c * 16;
                cpa16(so,           aH + (size_t)row * sA + k0 + c * 8);
                cpa16(so + T_BYTES, aL + (size_t)row * sA + k0 + c * 8);
            }
            #pragma unroll
            for (int i = 0; i < 2; i++) {
                int idx = tid + i * 256;
                int row = idx >> 3, c = idx & 7;
                uint32_t so = st + 2 * T_BYTES + row * ASTRIDE + c * 16;
                cpa16(so,           bH + (size_t)row * sB + k0 + c * 8);
                cpa16(so + T_BYTES, bL + (size_t)row * sB + k0 + c * 8);
            }
        }
        cpa_commit();
    };

    issue(0); issue(1);

    const int wid = tid >> 5, lane = tid & 31;
    const int wk = wid >> 2;                 // 0/1 : handles kk = 2*wk + {0,1}
    const int wm = (wid >> 1) & 1;           // 32-row half
    const int wn = wid & 1;                  // 32-col half
    const uint32_t lrow = lane & 15;
    const uint32_t lcol = (lane >> 4) * 16;

    float acc[2][4][4];                      // [m16 tile][n8 tile][frag]
    #pragma unroll
    for (int i = 0; i < 2; i++)
        #pragma unroll
        for (int j = 0; j < 4; j++)
            #pragma unroll
            for (int t = 0; t < 4; t++) acc[i][j][t] = 0.f;

    for (int s = 0; s < Ksteps; ++s) {
        cpa_wait<1>();                 // stage s landed
        __syncthreads();               // all warps done with buffer (s-1)%3
        issue(s + 2);                  // refill freed buffer, overlaps compute
        const uint32_t st = sbase + (s % NSTAGE) * STAGE;
        #pragma unroll
        for (int j = 0; j < 2; ++j) {
            const int kk = wk * 2 + j;
            uint32_t aHf[2][4], aLf[2][4], bHf[2][4], bLf[2][4];
            #pragma unroll
            for (int am = 0; am < 2; am++) {
                uint32_t ad = st + (wm * 32 + am * 16 + lrow) * ASTRIDE + kk * 32 + lcol;
                ldm4(ad,           aHf[am]);
                ldm4(ad + T_BYTES, aLf[am]);
            }
            #pragma unroll
            for (int bt = 0; bt < 2; bt++) {
                uint32_t bd = st + 2 * T_BYTES + (wn * 32 + bt * 16 + lrow) * ASTRIDE + kk * 32 + lcol;
                ldm4(bd,           bHf[bt]);
                ldm4(bd + T_BYTES, bLf[bt]);
            }
            #pragma unroll
            for (int am = 0; am < 2; am++) {
                #pragma unroll
                for (int bt = 0; bt < 2; bt++) {
                    mma16816(acc[am][2*bt],   aHf[am], bHf[bt][0], bHf[bt][2]);
                    mma16816(acc[am][2*bt+1], aHf[am], bHf[bt][1], bHf[bt][3]);
                    mma16816(acc[am][2*bt],   aHf[am], bLf[bt][0], bLf[bt][2]);
                    mma16816(acc[am][2*bt+1], aHf[am], bLf[bt][1], bLf[bt][3]);
                    mma16816(acc[am][2*bt],   aLf[am], bHf[bt][0], bHf[bt][2]);
                    mma16816(acc[am][2*bt+1], aLf[am], bHf[bt][1], bHf[bt][3]);
                }
            }
        }
    }

    // ---- reduce wk=1 partial sums into wk=0 via SMEM (stages are dead now) ----
    __syncthreads();
    float* red = (float*)smem;               // 4 regions of [32][34] floats
    float* rbase = red + (wm * 2 + wn) * (32 * 34);
    if (wk == 1) {
        #pragma unroll
        for (int am = 0; am < 2; am++)
            #pragma unroll
            for (int an = 0; an < 4; an++)
                #pragma unroll
                for (int t = 0; t < 4; t++) {
                    int row = am * 16 + (lane >> 2) + (t >> 1) * 8;
                    int col = an * 8 + (lane & 3) * 2 + (t & 1);
                    rbase[row * 34 + col] = acc[am][an][t];
                }
    }
    __syncthreads();
    if (wk == 1) return;
    #pragma unroll
    for (int am = 0; am < 2; am++)
        #pragma unroll
        for (int an = 0; an < 4; an++)
            #pragma unroll
            for (int t = 0; t < 4; t++) {
                int row = am * 16 + (lane >> 2) + (t >> 1) * 8;
                int col = an * 8 + (lane & 3) * 2 + (t & 1);
                acc[am][an][t] += rbase[row * 34 + col];
            }

    // ---- epilogue (wk=0 warps only): registers -> global ----
    #pragma unroll
    for (int am = 0; am < 2; am++) {
        #pragma unroll
        for (int an = 0; an < 4; an++) {
            int m0 = mBase + wm * 32 + am * 16 + (lane >> 2);
            int g  = nBase + wn * 32 + an * 8 + (lane & 3) * 2;
            #pragma unroll
            for (int half = 0; half < 2; half++) {
                int m = m0 + half * 8;
                float v0 = acc[am][an][half * 2];
                float v1 = acc[am][an][half * 2 + 1];
                if (EP == 0) {                          // relu -> h hi/lo
                    v0 = fmaxf(v0 + biasP[g], 0.f);
                    v1 = fmaxf(v1 + biasP[g + 1], 0.f);
                    store_hilo(oHi, oLo, (size_t)m * HIDDEN + g, v0, v1);
                } else if (EP == 1) {                   // xsub fp32
                    v0 += biasP[g]; v1 += biasP[g + 1];
                    *(float2*)(o32 + (size_t)m * HIDDEN + g) = make_float2(v0, v1);
                } else if (EP == 2) {                   // qkv fp32 split
                    int which = g >> 9, lc = g & 511;
                    const float* bb = (which == 0) ? bq : (which == 1) ? bk : bv;
                    float* dst = (which == 0) ? oq : (which == 1) ? okk : ov;
                    v0 += bb[lc]; v1 += bb[lc + 1];
                    *(float2*)(dst + (size_t)m * HIDDEN + lc) = make_float2(v0, v1);
                } else if (EP == 3) {                   // t hi/lo
                    v0 += biasP[g]; v1 += biasP[g + 1];
                    store_hilo(oHi, oLo, (size_t)m * HIDDEN + g, v0, v1);
                } else {                                // out = . + bp + xsub, (b,s) order
                    v0 += biasP[g] + resid[(size_t)m * HIDDEN + g];
                    v1 += biasP[g + 1] + resid[(size_t)m * HIDDEN + g + 1];
                    int bb2 = m & (BATCH - 1), ss = m >> 8;
                    *(float2*)(o32 + ((size_t)((bb2 << 3) + ss)) * HIDDEN + g) = make_float2(v0, v1);
                }
            }
        }
    }
}

// ---------------- LayerNorm: xsub fp32 -> xn hi/lo ----------------
__global__ __launch_bounds__(256) void ln_kernel(const float* __restrict__ lng,
                                                 const float* __restrict__ lnb)
{
    int r = blockIdx.x, t = threadIdx.x;
    const float* xs = g_xsub + (size_t)r * HIDDEN;
    float v0 = xs[t], v1 = xs[t + 256];
    float s = v0 + v1, q = v0 * v0 + v1 * v1;
    #pragma unroll
    for (int o = 16; o > 0; o >>= 1) {
        s += __shfl_xor_sync(0xFFFFFFFFu, s, o);
        q += __shfl_xor_sync(0xFFFFFFFFu, q, o);
    }
    __shared__ float ss[8], sq[8];
    int w = t >> 5, l = t & 31;
    if (l == 0) { ss[w] = s; sq[w] = q; }
    __syncthreads();
    if (w == 0) {
        float a = (l < 8) ? ss[l] : 0.f;
        float c = (l < 8) ? sq[l] : 0.f;
        #pragma unroll
        for (int o = 4; o > 0; o >>= 1) {
            a += __shfl_xor_sync(0xFFFFFFFFu, a, o);
            c += __shfl_xor_sync(0xFFFFFFFFu, c, o);
        }
        if (l == 0) { ss[0] = a; sq[0] = c; }
    }
    __syncthreads();
    float mean = ss[0] * (1.f / HIDDEN);
    float var  = sq[0] * (1.f / HIDDEN) - mean * mean;
    float inv  = rsqrtf(var + LN_EPS);
    float o0 = (v0 - mean) * inv * lng[t] + lnb[t];
    float o1 = (v1 - mean) * inv * lng[t + 256] + lnb[t + 256];
    size_t base = (size_t)r * HIDDEN;
    __nv_bfloat16 h0 = __float2bfloat16(o0);
    __nv_bfloat16 h1 = __float2bfloat16(o1);
    g_xn_hi[base + t] = h0;
    g_xn_lo[base + t] = __float2bfloat16(o0 - __bfloat162float(h0));
    g_xn_hi[base + t + 256] = h1;
    g_xn_lo[base + t + 256] = __float2bfloat16(o1 - __bfloat162float(h1));
}

// ---------------- attention: q,k,v fp32 -> ctx hi/lo ----------------
__global__ __launch_bounds__(256) void attn_kernel()
{
    __shared__ float q_s[NUM_SUBNETS][520];
    __shared__ float k_s[NUM_SUBNETS][520];
    __shared__ float sc[HEADS][NUM_SUBNETS][NUM_SUBNETS];

    int b = blockIdx.x;
    int tid = threadIdx.x;

    for (int i = tid; i < NUM_SUBNETS * HIDDEN; i += 256) {
        int m = i >> 9, c = i & 511;
        size_t gi = ((size_t)(m * BATCH + b)) * HIDDEN + c;
        q_s[m][c] = g_q[gi];
        k_s[m][c] = g_k[gi];
    }
    __syncthreads();

    int h = tid >> 5, l = tid & 31;

    #pragma unroll
    for (int pp = 0; pp < 2; pp++) {
        int p = l + pp * 32;
        int m = p >> 3, n = p & 7;
        const float* qp = &q_s[m][h * HEAD_DIM];
        const float* kp = &k_s[n][h * HEAD_DIM];
        float sv = 0.f;
        #pragma unroll
        for (int d = 0; d < HEAD_DIM; d++) sv += qp[d] * kp[d];
        sv *= 0.125f;
        sc[h][m][n] = (m == n) ? 0.f : sv;
    }
    __syncwarp();

    if (l < NUM_SUBNETS) {
        float mx = -1e30f;
        #pragma unroll
        for (int n = 0; n < 8; n++) mx = fmaxf(mx, sc[h][l][n]);
        float e[8], sum = 0.f;
        #pragma unroll
        for (int n = 0; n < 8; n++) { e[n] = expf(sc[h][l][n] - mx); sum += e[n]; }
        float inv = 1.f / sum;
        #pragma unroll
        for (int n = 0; n < 8; n++) sc[h][l][n] = e[n] * inv;
    }
    __syncwarp();

    #pragma unroll
    for (int dd = 0; dd < 2; dd++) {
        int d = l + dd * 32;
        float vv[8];
        #pragma unroll
        for (int n = 0; n < 8; n++)
            vv[n] = g_v[((size_t)(n * BATCH + b)) * HIDDEN + h * HEAD_DIM + d];
        #pragma unroll
        for (int m = 0; m < 8; m++) {
            float cv = 0.f;
            #pragma unroll
            for (int n = 0; n < 8; n++) cv += sc[h][m][n] * vv[n];
            size_t off = ((size_t)(m * BATCH + b)) * HIDDEN + h * HEAD_DIM + d;
            __nv_bfloat16 hi = __float2bfloat16(cv);
            g_ctx_hi[off] = hi;
            g_ctx_lo[off] = __float2bfloat16(cv - __bfloat162float(hi));
        }
    }
}

// ---------------- launch ----------------
extern "C" void kernel_launch(void* const* d_in, const int* in_sizes, int n_in,
                              void* d_out, int out_size)
{
    (void)in_sizes; (void)n_in; (void)out_size;
    const float* x    = (const float*)d_in[0];
    const float* W1   = (const float*)d_in[2];
    const float* b1   = (const float*)d_in[3];
    const float* W2   = (const float*)d_in[4];
    const float* b2   = (const float*)d_in[5];
    const float* ln_g = (const float*)d_in[6];
    const float* ln_b = (const float*)d_in[7];
    const float* Wq   = (const float*)d_in[8];
    const float* bq   = (const float*)d_in[9];
    const float* Wk   = (const float*)d_in[10];
    const float* bk   = (const float*)d_in[11];
    const float* Wv   = (const float*)d_in[12];
    const float* bv   = (const float*)d_in[13];
    const float* Wo   = (const float*)d_in[14];
    const float* bo   = (const float*)d_in[15];
    const float* Wp   = (const float*)d_in[16];
    const float* bp   = (const float*)d_in[17];
    float* out = (float*)d_out;

    __nv_bfloat16 *flat_hi, *flat_lo, *W1T_hi, *W1T_lo, *W2T_hi, *W2T_lo;
    __nv_bfloat16 *WqkvT_hi, *WqkvT_lo, *WoT_hi, *WoT_lo, *WpT_hi, *WpT_lo;
    __nv_bfloat16 *h_hi, *h_lo, *xn_hi, *xn_lo, *ctx_hi, *ctx_lo, *t_hi, *t_lo;
    float *xsub, *pq, *pk, *pv;
    cudaGetSymbolAddress((void**)&flat_hi, g_flat_hi);
    cudaGetSymbolAddress((void**)&flat_lo, g_flat_lo);
    cudaGetSymbolAddress((void**)&W1T_hi,  g_W1T_hi);
    cudaGetSymbolAddress((void**)&W1T_lo,  g_W1T_lo);
    cudaGetSymbolAddress((void**)&W2T_hi,  g_W2T_hi);
    cudaGetSymbolAddress((void**)&W2T_lo,  g_W2T_lo);
    cudaGetSymbolAddress((void**)&WqkvT_hi, g_WqkvT_hi);
    cudaGetSymbolAddress((void**)&WqkvT_lo, g_WqkvT_lo);
    cudaGetSymbolAddress((void**)&WoT_hi,  g_WoT_hi);
    cudaGetSymbolAddress((void**)&WoT_lo,  g_WoT_lo);
    cudaGetSymbolAddress((void**)&WpT_hi,  g_WpT_hi);
    cudaGetSymbolAddress((void**)&WpT_lo,  g_WpT_lo);
    cudaGetSymbolAddress((void**)&h_hi,    g_h_hi);
    cudaGetSymbolAddress((void**)&h_lo,    g_h_lo);
    cudaGetSymbolAddress((void**)&xn_hi,   g_xn_hi);
    cudaGetSymbolAddress((void**)&xn_lo,   g_xn_lo);
    cudaGetSymbolAddress((void**)&ctx_hi,  g_ctx_hi);
    cudaGetSymbolAddress((void**)&ctx_lo,  g_ctx_lo);
    cudaGetSymbolAddress((void**)&t_hi,    g_t_hi);
    cudaGetSymbolAddress((void**)&t_lo,    g_t_lo);
    cudaGetSymbolAddress((void**)&xsub,    g_xsub);
    cudaGetSymbolAddress((void**)&pq,      g_q);
    cudaGetSymbolAddress((void**)&pk,      g_k);
    cudaGetSymbolAddress((void**)&pv,      g_v);

    cudaFuncSetAttribute(tc_gemm<0>, cudaFuncAttributeMaxDynamicSharedMemorySize, GEMM_SMEM);
    cudaFuncSetAttribute(tc_gemm<1>, cudaFuncAttributeMaxDynamicSharedMemorySize, GEMM_SMEM);
    cudaFuncSetAttribute(tc_gemm<2>, cudaFuncAttributeMaxDynamicSharedMemorySize, GEMM_SMEM);
    cudaFuncSetAttribute(tc_gemm<3>, cudaFuncAttributeMaxDynamicSharedMemorySize, GEMM_SMEM);
    cudaFuncSetAttribute(tc_gemm<4>, cudaFuncAttributeMaxDynamicSharedMemorySize, GEMM_SMEM);

    // ---- input conversions ----
    extract_kernel<<<(ROWS * KPAD1 / 4 + 255) / 256, 256>>>(x);
    wconv_w1_kernel<<<dim3(KPAD1 / 32, HIDDEN / 32, NUM_SUBNETS), 256>>>(W1);

    W13 wa;
    for (int z = 0; z < 8; z++) {
        wa.src[z] = W2 + (size_t)z * HIDDEN * HIDDEN;
        wa.dhi[z] = W2T_hi + (size_t)z * HIDDEN * HIDDEN;
        wa.dlo[z] = W2T_lo + (size_t)z * HIDDEN * HIDDEN;
    }
    const float* srcs[5] = { Wq, Wk, Wv, Wo, Wp };
    __nv_bfloat16* dhis[5] = { WqkvT_hi, WqkvT_hi + 512 * 512, WqkvT_hi + 1024 * 512, WoT_hi, WpT_hi };
    __nv_bfloat16* dlos[5] = { WqkvT_lo, WqkvT_lo + 512 * 512, WqkvT_lo + 1024 * 512, WoT_lo, WpT_lo };
    for (int z = 0; z < 5; z++) {
        wa.src[8 + z] = srcs[z];
        wa.dhi[8 + z] = dhis[z];
        wa.dlo[8 + z] = dlos[z];
    }
    wconv512_kernel<<<dim3(16, 16, 13), 256>>>(wa);

    dim3 g512(HIDDEN / BN, ROWS / BM);        // 8 x 32 = 256 CTAs
    dim3 gqkv(3 * HIDDEN / BN, ROWS / BM);    // 24 x 32 = 768 CTAs

    // GEMM1: h = relu(flat @ W1 + b1)
    tc_gemm<0><<<g512, 256, GEMM_SMEM>>>(flat_hi, flat_lo, KPAD1, W1T_hi, W1T_lo, KPAD1,
        (long)HIDDEN * KPAD1, KPAD1 / BK, b1, nullptr, h_hi, h_lo,
        nullptr, nullptr, nullptr, nullptr, nullptr, nullptr, nullptr);
    // GEMM2: xsub = h @ W2 + b2
    tc_gemm<1><<<g512, 256, GEMM_SMEM>>>(h_hi, h_lo, HIDDEN, W2T_hi, W2T_lo, HIDDEN,
        (long)HIDDEN * HIDDEN, HIDDEN / BK, b2, xsub, nullptr, nullptr,
        nullptr, nullptr, nullptr, nullptr, nullptr, nullptr, nullptr);
    // LN -> xn hi/lo
    ln_kernel<<<ROWS, 256>>>(ln_g, ln_b);
    // QKV fused
    tc_gemm<2><<<gqkv, 256, GEMM_SMEM>>>(xn_hi, xn_lo, HIDDEN, WqkvT_hi, WqkvT_lo, HIDDEN,
        0L, HIDDEN / BK, nullptr, nullptr, nullptr, nullptr,
        nullptr, pq, pk, pv, bq, bk, bv);
    // attention -> ctx hi/lo
    attn_kernel<<<BATCH, 256>>>();
    // O: t = ctx @ Wo + bo
    tc_gemm<3><<<g512, 256, GEMM_SMEM>>>(ctx_hi, ctx_lo, HIDDEN, WoT_hi, WoT_lo, HIDDEN,
        0L, HIDDEN / BK, bo, nullptr, t_hi, t_lo,
        nullptr, nullptr, nullptr, nullptr, nullptr, nullptr, nullptr);
    // P: out = t @ Wp + bp + xsub (permuted to (b,s))
    tc_gemm<4><<<g512, 256, GEMM_SMEM>>>(t_hi, t_lo, HIDDEN, WpT_hi, WpT_lo, HIDDEN,
        0L, HIDDEN / BK, bp, out, nullptr, nullptr,
        xsub, nullptr, nullptr, nullptr, nullptr, nullptr, nullptr);
}